// round 4
// baseline (speedup 1.0000x reference)
#include <cuda_runtime.h>

// ---------------------------------------------------------------------------
// 3-layer GCN, symmetric norm D^{-1/2}(A+I)D^{-1/2}, self-loops.
// N=50000, E=640000, features 128 -> 128 -> 128 -> 64.
// edge_index dtype auto-detected (int32 vs int64) on device.
// __device__ scratch referenced ONLY inside device code.
// ---------------------------------------------------------------------------

#define MAX_N 50048
#define MAX_E 640000

__device__ __align__(16) float g_H[MAX_N * 128];   // H = X @ W
__device__ __align__(16) float g_B[MAX_N * 128];   // layer output / accumulator
__device__ __align__(16) float g_norm[MAX_E];      // per-edge norm
__device__ __align__(16) int2  g_edge[MAX_E];      // (src, dst) int32
__device__ float g_dinv[MAX_N];                    // deg counter -> (deg+1)^-1/2
__device__ int   g_is64;                           // edge dtype flag

// ---------------------------------------------------------------------------
// Detect edge_index dtype. Samples 128 int64 words from the first E words
// (always within the buffer for both dtypes). int32 data interpreted as
// int64 packs two edge ids -> values >= 2^32 almost surely.
// ---------------------------------------------------------------------------
__global__ void detect_dtype_kernel(const void* __restrict__ ei, int E, int N) {
    if (threadIdx.x == 0 && blockIdx.x == 0) {
        const long long* p = (const long long*)ei;
        int ok = 1;
        int take = E < 128 ? E : 128;
        for (int i = 0; i < take; i++) {
            long long v = p[i];
            if (v < 0 || v >= (long long)N) { ok = 0; break; }
        }
        g_is64 = ok;
    }
}

__global__ void zero_dinv_kernel(int n) {
    int i = blockIdx.x * blockDim.x + threadIdx.x;
    if (i < n) g_dinv[i] = 0.0f;
}

// Decode edges (dtype branch), pack to int2, count in-degree at dst.
__global__ void prep_edges_kernel(const void* __restrict__ ei, int E) {
    int e = blockIdx.x * blockDim.x + threadIdx.x;
    if (e >= E) return;
    int s, d;
    if (g_is64) {
        const long long* p = (const long long*)ei;
        s = (int)p[e];
        d = (int)p[E + e];
    } else {
        const int* p = (const int*)ei;
        s = p[e];
        d = p[E + e];
    }
    g_edge[e] = make_int2(s, d);
    atomicAdd(&g_dinv[d], 1.0f);
}

__global__ void dinv_kernel(int n) {
    int i = blockIdx.x * blockDim.x + threadIdx.x;
    if (i < n) g_dinv[i] = rsqrtf(g_dinv[i] + 1.0f);
}

__global__ void norm_kernel(int E) {
    int e = blockIdx.x * blockDim.x + threadIdx.x;
    if (e >= E) return;
    int2 sd = g_edge[e];
    g_norm[e] = g_dinv[sd.x] * g_dinv[sd.y];
}

// ---------------------------------------------------------------------------
// GEMM: g_H[N, FOUT] = X[N, 128] @ W[128, FOUT]
// 256 threads: c = tid&63 (column), rgrp = tid>>6 owns 4 rows.
// ---------------------------------------------------------------------------
template <int FOUT, bool FROM_GB>
__global__ void gemm_kernel(const float* __restrict__ Xin,
                            const float* __restrict__ W, int N) {
    __shared__ float Ws[128][65];
    __shared__ float Xs[16][129];

    const float* __restrict__ X = FROM_GB ? (const float*)g_B : Xin;

    const int tid = threadIdx.x;
    const int c = tid & 63;
    const int rgrp = tid >> 6;  // 0..3
    const int ctile = blockIdx.y * 64;
    const int rowBase = blockIdx.x * 64;

    for (int i = tid; i < 128 * 64; i += 256) {
        int k = i >> 6, cc = i & 63;
        Ws[k][cc] = W[k * FOUT + ctile + cc];
    }

    for (int chunk = 0; chunk < 4; chunk++) {
        __syncthreads();
        for (int i = tid; i < 16 * 128; i += 256) {
            int rr = i >> 7, cc = i & 127;
            int r = rowBase + chunk * 16 + rr;
            Xs[rr][cc] = (r < N) ? X[r * 128 + cc] : 0.0f;
        }
        __syncthreads();

        float a0 = 0.f, a1 = 0.f, a2 = 0.f, a3 = 0.f;
        const int rb = rgrp * 4;
        #pragma unroll
        for (int k = 0; k < 128; k++) {
            float w = Ws[k][c];
            a0 = fmaf(Xs[rb + 0][k], w, a0);
            a1 = fmaf(Xs[rb + 1][k], w, a1);
            a2 = fmaf(Xs[rb + 2][k], w, a2);
            a3 = fmaf(Xs[rb + 3][k], w, a3);
        }

        int row = rowBase + chunk * 16 + rb;
        float acc[4] = {a0, a1, a2, a3};
        #pragma unroll
        for (int j = 0; j < 4; j++)
            if (row + j < N) g_H[(size_t)(row + j) * FOUT + ctile + c] = acc[j];
    }
}

// ---------------------------------------------------------------------------
// Init output with self-loop + bias: OUT = H * dinv^2 + b (float4)
// ---------------------------------------------------------------------------
template <int F, bool TO_GB>
__global__ void init_out_kernel(const float* __restrict__ b,
                                float* __restrict__ outp, int N) {
    int idx = blockIdx.x * blockDim.x + threadIdx.x;  // float4 index
    int total = N * (F / 4);
    if (idx >= total) return;
    int row = idx / (F / 4);
    int c4 = idx % (F / 4);
    float di = g_dinv[row];
    float s = di * di;
    float4 h = reinterpret_cast<const float4*>(g_H)[idx];
    float4 bb = reinterpret_cast<const float4*>(b)[c4];
    float4 v = make_float4(fmaf(h.x, s, bb.x), fmaf(h.y, s, bb.y),
                           fmaf(h.z, s, bb.z), fmaf(h.w, s, bb.w));
    float4* dst = TO_GB ? reinterpret_cast<float4*>(g_B)
                        : reinterpret_cast<float4*>(outp);
    dst[idx] = v;
}

// ---------------------------------------------------------------------------
// Vectorized no-return reduction (sm_90+)
// ---------------------------------------------------------------------------
__device__ __forceinline__ void red_add_v4(float* p, float a, float b,
                                           float c, float d) {
    asm volatile("red.global.add.v4.f32 [%0], {%1, %2, %3, %4};"
                 :: "l"(p), "f"(a), "f"(b), "f"(c), "f"(d)
                 : "memory");
}

// ---------------------------------------------------------------------------
// Edge scatter: OUT[dst] += H[src] * norm
// F=128: 32 lanes/edge; F=64: 16 lanes/edge (no idle lanes).
// ---------------------------------------------------------------------------
template <int F, bool TO_GB>
__global__ void scatter_kernel(float* __restrict__ outp, int E) {
    const int LANES = F / 4;
    int g = blockIdx.x * blockDim.x + threadIdx.x;
    int e = g / LANES;
    int lane = g % LANES;
    if (e >= E) return;

    int2 sd = g_edge[e];
    float nm = g_norm[e];

    float4 v = reinterpret_cast<const float4*>(g_H + (size_t)sd.x * F)[lane];
    float* dstbase = TO_GB ? g_B : outp;
    float* ag = dstbase + (size_t)sd.y * F + lane * 4;
    red_add_v4(ag, v.x * nm, v.y * nm, v.z * nm, v.w * nm);
}

__global__ void relu_kernel(int total4) {
    int idx = blockIdx.x * blockDim.x + threadIdx.x;
    if (idx >= total4) return;
    float4* p = reinterpret_cast<float4*>(g_B);
    float4 v = p[idx];
    v.x = fmaxf(v.x, 0.f); v.y = fmaxf(v.y, 0.f);
    v.z = fmaxf(v.z, 0.f); v.w = fmaxf(v.w, 0.f);
    p[idx] = v;
}

// ---------------------------------------------------------------------------
// Launch — pure kernel launches; only harness pointers cross the boundary.
// ---------------------------------------------------------------------------
extern "C" void kernel_launch(void* const* d_in, const int* in_sizes, int n_in,
                              void* d_out, int out_size) {
    const float* x  = (const float*)d_in[0];
    const void*  ei = d_in[1];
    const float* W1 = (const float*)d_in[2];
    const float* b1 = (const float*)d_in[3];
    const float* W2 = (const float*)d_in[4];
    const float* b2 = (const float*)d_in[5];
    const float* W3 = (const float*)d_in[6];
    const float* b3 = (const float*)d_in[7];
    float* out = (float*)d_out;

    const int N = in_sizes[0] / 128;
    const int E = in_sizes[1] / 2;
    const int T = 256;

    // ---- dtype detect + normalization + edge prep (shared) ----
    detect_dtype_kernel<<<1, 32>>>(ei, E, N);
    zero_dinv_kernel<<<(N + T - 1) / T, T>>>(N);
    prep_edges_kernel<<<(E + T - 1) / T, T>>>(ei, E);
    dinv_kernel<<<(N + T - 1) / T, T>>>(N);
    norm_kernel<<<(E + T - 1) / T, T>>>(E);

    const int sc128 = (E * 32 + T - 1) / T;
    const int sc64  = (E * 16 + T - 1) / T;
    const int ew128 = (N * 32 + T - 1) / T;
    const int ew64  = (N * 16 + T - 1) / T;

    // ---- layer 1: x @ W1, relu ----
    {
        dim3 g((N + 63) / 64, 2);
        gemm_kernel<128, false><<<g, 256>>>(x, W1, N);
        init_out_kernel<128, true><<<ew128, T>>>(b1, nullptr, N);
        scatter_kernel<128, true><<<sc128, T>>>(nullptr, E);
        relu_kernel<<<ew128, T>>>(N * 32);
    }

    // ---- layer 2: B @ W2, relu ----
    {
        dim3 g((N + 63) / 64, 2);
        gemm_kernel<128, true><<<g, 256>>>(nullptr, W2, N);
        init_out_kernel<128, true><<<ew128, T>>>(b2, nullptr, N);
        scatter_kernel<128, true><<<sc128, T>>>(nullptr, E);
        relu_kernel<<<ew128, T>>>(N * 32);
    }

    // ---- layer 3: B @ W3 -> d_out, no relu ----
    {
        dim3 g((N + 63) / 64, 1);
        gemm_kernel<64, true><<<g, 256>>>(nullptr, W3, N);
        init_out_kernel<64, false><<<ew64, T>>>(b3, out, N);
        scatter_kernel<64, false><<<sc64, T>>>(out, E);
    }
}

// round 5
// speedup vs baseline: 1.2632x; 1.2632x over previous
#include <cuda_runtime.h>

// ---------------------------------------------------------------------------
// 3-layer GCN, symmetric norm D^{-1/2}(A+I)D^{-1/2}, self-loops.
// N=50000, E=640000, features 128 -> 128 -> 128 -> 64.
// R5: register-tiled SGEMM with fused self-loop+bias epilogue, relu fused
// into next GEMM's loads. Scatter via red.global.add.v4.f32.
// ---------------------------------------------------------------------------

#define MAX_N 50048
#define MAX_E 640000

__device__ __align__(16) float g_H[MAX_N * 128];   // H = X @ W
__device__ __align__(16) float g_B[MAX_N * 128];   // layer accumulator/output
__device__ __align__(16) float g_norm[MAX_E];      // per-edge norm
__device__ __align__(16) int2  g_edge[MAX_E];      // (src, dst) int32
__device__ float g_dinv[MAX_N];                    // deg -> (deg+1)^-1/2
__device__ int   g_is64;

// ---------------------------------------------------------------------------
// Prep: dtype detect, degree, dinv, per-edge norm
// ---------------------------------------------------------------------------
__global__ void detect_dtype_kernel(const void* __restrict__ ei, int E, int N) {
    if (threadIdx.x == 0 && blockIdx.x == 0) {
        const long long* p = (const long long*)ei;
        int ok = 1;
        int take = E < 128 ? E : 128;
        for (int i = 0; i < take; i++) {
            long long v = p[i];
            if (v < 0 || v >= (long long)N) { ok = 0; break; }
        }
        g_is64 = ok;
    }
}

__global__ void zero_dinv_kernel(int n) {
    int i = blockIdx.x * blockDim.x + threadIdx.x;
    if (i < n) g_dinv[i] = 0.0f;
}

__global__ void prep_edges_kernel(const void* __restrict__ ei, int E) {
    int e = blockIdx.x * blockDim.x + threadIdx.x;
    if (e >= E) return;
    int s, d;
    if (g_is64) {
        const long long* p = (const long long*)ei;
        s = (int)p[e];
        d = (int)p[E + e];
    } else {
        const int* p = (const int*)ei;
        s = p[e];
        d = p[E + e];
    }
    g_edge[e] = make_int2(s, d);
    atomicAdd(&g_dinv[d], 1.0f);
}

__global__ void dinv_kernel(int n) {
    int i = blockIdx.x * blockDim.x + threadIdx.x;
    if (i < n) g_dinv[i] = rsqrtf(g_dinv[i] + 1.0f);
}

__global__ void norm_kernel(int E) {
    int e = blockIdx.x * blockDim.x + threadIdx.x;
    if (e >= E) return;
    int2 sd = g_edge[e];
    g_norm[e] = g_dinv[sd.x] * g_dinv[sd.y];
}

// ---------------------------------------------------------------------------
// Register-tiled SGEMM with fused epilogue.
//   g_H[row][BN]  = X[row] @ W          (raw, consumed by scatter gather)
//   OUT[row][BN]  = H*dinv[row]^2 + b   (self-loop + bias init; scatter reds
//                                        on top of this)
// BM=128, BK=16, BN=FOUT. 256 threads; thread tile 8 x (BN/16).
// RELU applies fmaxf on the X load (X = pre-activation from previous layer).
// ---------------------------------------------------------------------------
template <int BN, bool RELU, bool FROM_GB, bool OUT_GB>
__global__ __launch_bounds__(256, 2)
void gemm_fused_kernel(const float* __restrict__ Xin,
                       const float* __restrict__ W,
                       const float* __restrict__ bias,
                       float* __restrict__ outp, int N) {
    constexpr int BM = 128, BK = 16;
    constexpr int TN = BN / 16;               // 8 or 4
    constexpr int WI = (BK * BN) / 1024;      // W-tile float4 loads per thread

    __shared__ float Xs[BK][BM + 4];          // transposed, padded
    __shared__ float Ws[BK][BN];

    const float* __restrict__ X = FROM_GB ? (const float*)g_B : Xin;
    float* __restrict__ OUT = OUT_GB ? (float*)g_B : outp;

    const int tid = threadIdx.x;
    const int tx = tid & 15;                  // 0..15 (column group)
    const int ty = tid >> 4;                  // 0..15 (row group)
    const int rowBase = blockIdx.x * BM;

    float acc[8][TN] = {};

    for (int kc = 0; kc < 128; kc += BK) {
        // ---- load X tile (BM x BK), store transposed into Xs ----
        #pragma unroll
        for (int i = 0; i < 2; i++) {
            int j = tid + 256 * i;            // float4 slot 0..511
            int row = j >> 2;                 // 0..127
            int kq = j & 3;                   // 0..3 (16B group within BK)
            int r = rowBase + row;
            float4 v = make_float4(0.f, 0.f, 0.f, 0.f);
            if (r < N)
                v = *reinterpret_cast<const float4*>(&X[(size_t)r * 128 + kc + kq * 4]);
            if (RELU) {
                v.x = fmaxf(v.x, 0.f); v.y = fmaxf(v.y, 0.f);
                v.z = fmaxf(v.z, 0.f); v.w = fmaxf(v.w, 0.f);
            }
            Xs[kq * 4 + 0][row] = v.x;
            Xs[kq * 4 + 1][row] = v.y;
            Xs[kq * 4 + 2][row] = v.z;
            Xs[kq * 4 + 3][row] = v.w;
        }
        // ---- load W tile (BK x BN) ----
        #pragma unroll
        for (int i = 0; i < WI; i++) {
            int j = tid + 256 * i;            // float4 slot
            int kk = j / (BN / 4);
            int cc = j % (BN / 4);
            *reinterpret_cast<float4*>(&Ws[kk][cc * 4]) =
                *reinterpret_cast<const float4*>(&W[(size_t)(kc + kk) * BN + cc * 4]);
        }
        __syncthreads();

        // ---- compute ----
        #pragma unroll
        for (int k = 0; k < BK; k++) {
            float a[8], b[TN];
            #pragma unroll
            for (int i = 0; i < 8; i += 4)
                *reinterpret_cast<float4*>(&a[i]) =
                    *reinterpret_cast<const float4*>(&Xs[k][ty * 8 + i]);
            #pragma unroll
            for (int j = 0; j < TN; j += 4)
                *reinterpret_cast<float4*>(&b[j]) =
                    *reinterpret_cast<const float4*>(&Ws[k][tx * TN + j]);
            #pragma unroll
            for (int i = 0; i < 8; i++)
                #pragma unroll
                for (int j = 0; j < TN; j++)
                    acc[i][j] = fmaf(a[i], b[j], acc[i][j]);
        }
        __syncthreads();
    }

    // ---- fused epilogue: raw H + self-loop/bias init ----
    float bb[TN];
    #pragma unroll
    for (int j = 0; j < TN; j++) bb[j] = bias[tx * TN + j];

    #pragma unroll
    for (int i = 0; i < 8; i++) {
        int row = rowBase + ty * 8 + i;
        if (row >= N) break;
        float di = g_dinv[row];
        float s = di * di;
        float h4[TN], o4[TN];
        #pragma unroll
        for (int j = 0; j < TN; j++) {
            h4[j] = acc[i][j];
            o4[j] = fmaf(h4[j], s, bb[j]);
        }
        size_t base = (size_t)row * BN + tx * TN;
        #pragma unroll
        for (int j = 0; j < TN; j += 4) {
            *reinterpret_cast<float4*>(&g_H[base + j]) =
                *reinterpret_cast<const float4*>(&h4[j]);
            *reinterpret_cast<float4*>(&OUT[base + j]) =
                *reinterpret_cast<const float4*>(&o4[j]);
        }
    }
}

// ---------------------------------------------------------------------------
// Vectorized no-return reduction (sm_90+)
// ---------------------------------------------------------------------------
__device__ __forceinline__ void red_add_v4(float* p, float a, float b,
                                           float c, float d) {
    asm volatile("red.global.add.v4.f32 [%0], {%1, %2, %3, %4};"
                 :: "l"(p), "f"(a), "f"(b), "f"(c), "f"(d)
                 : "memory");
}

// ---------------------------------------------------------------------------
// Edge scatter: OUT[dst] += H[src] * norm
// ---------------------------------------------------------------------------
template <int F, bool TO_GB>
__global__ void scatter_kernel(float* __restrict__ outp, int E) {
    const int LANES = F / 4;
    int g = blockIdx.x * blockDim.x + threadIdx.x;
    int e = g / LANES;
    int lane = g % LANES;
    if (e >= E) return;

    int2 sd = g_edge[e];
    float nm = g_norm[e];

    float4 v = reinterpret_cast<const float4*>(g_H + (size_t)sd.x * F)[lane];
    float* dstbase = TO_GB ? g_B : outp;
    float* ag = dstbase + (size_t)sd.y * F + lane * 4;
    red_add_v4(ag, v.x * nm, v.y * nm, v.z * nm, v.w * nm);
}

// ---------------------------------------------------------------------------
// Launch
// ---------------------------------------------------------------------------
extern "C" void kernel_launch(void* const* d_in, const int* in_sizes, int n_in,
                              void* d_out, int out_size) {
    const float* x  = (const float*)d_in[0];
    const void*  ei = d_in[1];
    const float* W1 = (const float*)d_in[2];
    const float* b1 = (const float*)d_in[3];
    const float* W2 = (const float*)d_in[4];
    const float* b2 = (const float*)d_in[5];
    const float* W3 = (const float*)d_in[6];
    const float* b3 = (const float*)d_in[7];
    float* out = (float*)d_out;

    const int N = in_sizes[0] / 128;
    const int E = in_sizes[1] / 2;
    const int T = 256;

    // ---- shared prep ----
    detect_dtype_kernel<<<1, 32>>>(ei, E, N);
    zero_dinv_kernel<<<(N + T - 1) / T, T>>>(N);
    prep_edges_kernel<<<(E + T - 1) / T, T>>>(ei, E);
    dinv_kernel<<<(N + T - 1) / T, T>>>(N);
    norm_kernel<<<(E + T - 1) / T, T>>>(E);

    const int gemmBlocks = (N + 127) / 128;
    const int sc128 = (E * 32 + T - 1) / T;
    const int sc64  = (E * 16 + T - 1) / T;

    // ---- layer 1: H = x@W1; B = H*dinv^2 + b1; B += scatter(H) ----
    gemm_fused_kernel<128, false, false, true><<<gemmBlocks, 256>>>(x, W1, b1, nullptr, N);
    scatter_kernel<128, true><<<sc128, T>>>(nullptr, E);

    // ---- layer 2: relu on read of B ----
    gemm_fused_kernel<128, true, true, true><<<gemmBlocks, 256>>>(nullptr, W2, b2, nullptr, N);
    scatter_kernel<128, true><<<sc128, T>>>(nullptr, E);

    // ---- layer 3: relu on read of B, output to d_out, no final relu ----
    gemm_fused_kernel<64, true, true, false><<<gemmBlocks, 256>>>(nullptr, W3, b3, out, N);
    scatter_kernel<64, false><<<sc64, T>>>(out, E);
}

// round 6
// speedup vs baseline: 1.6085x; 1.2734x over previous
#include <cuda_runtime.h>

// ---------------------------------------------------------------------------
// 3-layer GCN, symmetric norm D^{-1/2}(A+I)D^{-1/2}, self-loops.
// N=50000, E=640000, features 128 -> 128 -> 128 -> 64.
// R6: FFMA2 (f32x2) register-tiled GEMM + CSR segmented-reduction aggregation
// (counting sort by dst) replacing atomic scatter.
// ---------------------------------------------------------------------------

#define MAX_N 50048
#define MAX_E 640000

__device__ __align__(16) float g_H[MAX_N * 128];    // H = X @ W
__device__ __align__(16) float g_B[MAX_N * 128];    // layer accumulator/output
__device__ __align__(16) float g_enorm[MAX_E];      // norm per SORTED edge
__device__ __align__(16) int   g_src[MAX_E];        // src per SORTED edge
__device__ int   g_rowptr[MAX_N + 1];               // CSR row pointers (by dst)
__device__ int   g_cnt[MAX_N];                      // counter / cursor
__device__ float g_dinv[MAX_N];
__device__ int   g_is64;

// ---------------------------------------------------------------------------
// f32x2 helpers
// ---------------------------------------------------------------------------
__device__ __forceinline__ unsigned long long dup_f32(float w) {
    unsigned long long r;
    asm("mov.b64 %0, {%1, %1};" : "=l"(r) : "f"(w));
    return r;
}
__device__ __forceinline__ void ffma2(unsigned long long& d,
                                      unsigned long long a,
                                      unsigned long long b) {
    asm("fma.rn.f32x2 %0, %1, %2, %0;" : "+l"(d) : "l"(a), "l"(b));
}
__device__ __forceinline__ void unpack2(unsigned long long v, float& lo, float& hi) {
    asm("mov.b64 {%0, %1}, %2;" : "=f"(lo), "=f"(hi) : "l"(v));
}

// ---------------------------------------------------------------------------
// Prep
// ---------------------------------------------------------------------------
__global__ void detect_dtype_kernel(const void* __restrict__ ei, int E, int N) {
    if (threadIdx.x == 0 && blockIdx.x == 0) {
        const long long* p = (const long long*)ei;
        int ok = 1;
        int take = E < 128 ? E : 128;
        for (int i = 0; i < take; i++) {
            long long v = p[i];
            if (v < 0 || v >= (long long)N) { ok = 0; break; }
        }
        g_is64 = ok;
    }
}

__global__ void zero_cnt_kernel(int n) {
    int i = blockIdx.x * blockDim.x + threadIdx.x;
    if (i < n) g_cnt[i] = 0;
}

__device__ __forceinline__ void decode_edge(const void* ei, int E, int e,
                                            int& s, int& d) {
    if (g_is64) {
        const long long* p = (const long long*)ei;
        s = (int)p[e];
        d = (int)p[E + e];
    } else {
        const int* p = (const int*)ei;
        s = p[e];
        d = p[E + e];
    }
}

__global__ void count_kernel(const void* __restrict__ ei, int E) {
    int e = blockIdx.x * blockDim.x + threadIdx.x;
    if (e >= E) return;
    int s, d;
    decode_edge(ei, E, e, s, d);
    atomicAdd(&g_cnt[d], 1);
}

__global__ void dinv_kernel(int n) {
    int i = blockIdx.x * blockDim.x + threadIdx.x;
    if (i < n) g_dinv[i] = rsqrtf((float)g_cnt[i] + 1.0f);
}

// Exclusive scan of g_cnt -> g_rowptr, zero g_cnt (cursor). Single block.
__global__ void scan_kernel(int n) {
    __shared__ int warpsum[32];
    __shared__ int carry;
    int tid = threadIdx.x, lane = tid & 31, wid = tid >> 5;
    if (tid == 0) carry = 0;
    __syncthreads();
    for (int base = 0; base < n; base += 1024) {
        int i = base + tid;
        int v = (i < n) ? g_cnt[i] : 0;
        int x = v;
        #pragma unroll
        for (int off = 1; off < 32; off <<= 1) {
            int t = __shfl_up_sync(0xffffffffu, x, off);
            if (lane >= off) x += t;
        }
        if (lane == 31) warpsum[wid] = x;
        __syncthreads();
        if (wid == 0) {
            int w = warpsum[lane];
            #pragma unroll
            for (int off = 1; off < 32; off <<= 1) {
                int t = __shfl_up_sync(0xffffffffu, w, off);
                if (lane >= off) w += t;
            }
            warpsum[lane] = w;
        }
        __syncthreads();
        int incl = x + (wid > 0 ? warpsum[wid - 1] : 0);
        int c = carry;
        __syncthreads();
        if (tid == 1023) carry = c + incl;
        if (i < n) {
            g_rowptr[i] = c + incl - v;
            g_cnt[i] = 0;
        }
        __syncthreads();
    }
    if (threadIdx.x == 0) g_rowptr[n] = carry;
}

// Fill sorted edge arrays + per-edge norm.
__global__ void fill_kernel(const void* __restrict__ ei, int E) {
    int e = blockIdx.x * blockDim.x + threadIdx.x;
    if (e >= E) return;
    int s, d;
    decode_edge(ei, E, e, s, d);
    int pos = g_rowptr[d] + atomicAdd(&g_cnt[d], 1);
    g_src[pos] = s;
    g_enorm[pos] = g_dinv[s] * g_dinv[d];
}

// ---------------------------------------------------------------------------
// FFMA2 register-tiled SGEMM, fused epilogue:
//   g_H = X @ W ; OUT = H*dinv^2 + bias
// BM=128, BK=16, BN=FOUT. 256 threads; thread tile 8 rows (4 f32x2 pairs) x TN.
// ---------------------------------------------------------------------------
template <int BN, bool RELU, bool FROM_GB, bool OUT_GB>
__global__ __launch_bounds__(256, 2)
void gemm_fused_kernel(const float* __restrict__ Xin,
                       const float* __restrict__ W,
                       const float* __restrict__ bias,
                       float* __restrict__ outp, int N) {
    constexpr int BM = 128, BK = 16;
    constexpr int TN = BN / 16;               // 8 or 4
    constexpr int WI = (BK * BN) / 1024;      // W float4 loads per thread

    __shared__ float Xs[BK][BM + 4];          // transposed
    __shared__ float Ws[BK][BN];

    const float* __restrict__ X = FROM_GB ? (const float*)g_B : Xin;
    float* __restrict__ OUT = OUT_GB ? (float*)g_B : outp;

    const int tid = threadIdx.x;
    const int tx = tid & 15;
    const int ty = tid >> 4;
    const int rowBase = blockIdx.x * BM;

    unsigned long long acc2[4][TN];
    #pragma unroll
    for (int i = 0; i < 4; i++)
        #pragma unroll
        for (int j = 0; j < TN; j++) acc2[i][j] = 0ull;

    for (int kc = 0; kc < 128; kc += BK) {
        #pragma unroll
        for (int i = 0; i < 2; i++) {
            int j = tid + 256 * i;
            int row = j >> 2;
            int kq = j & 3;
            int r = rowBase + row;
            float4 v = make_float4(0.f, 0.f, 0.f, 0.f);
            if (r < N)
                v = *reinterpret_cast<const float4*>(&X[(size_t)r * 128 + kc + kq * 4]);
            if (RELU) {
                v.x = fmaxf(v.x, 0.f); v.y = fmaxf(v.y, 0.f);
                v.z = fmaxf(v.z, 0.f); v.w = fmaxf(v.w, 0.f);
            }
            Xs[kq * 4 + 0][row] = v.x;
            Xs[kq * 4 + 1][row] = v.y;
            Xs[kq * 4 + 2][row] = v.z;
            Xs[kq * 4 + 3][row] = v.w;
        }
        #pragma unroll
        for (int i = 0; i < WI; i++) {
            int j = tid + 256 * i;
            int kk = j / (BN / 4);
            int cc = j % (BN / 4);
            *reinterpret_cast<float4*>(&Ws[kk][cc * 4]) =
                *reinterpret_cast<const float4*>(&W[(size_t)(kc + kk) * BN + cc * 4]);
        }
        __syncthreads();

        #pragma unroll
        for (int k = 0; k < BK; k++) {
            // 8 rows as 4 packed f32x2 (rows are consecutive in transposed Xs)
            const ulonglong2* ap =
                reinterpret_cast<const ulonglong2*>(&Xs[k][ty * 8]);
            ulonglong2 a01 = ap[0];
            ulonglong2 a23 = ap[1];
            unsigned long long a2[4] = {a01.x, a01.y, a23.x, a23.y};

            float bw[TN];
            #pragma unroll
            for (int j = 0; j < TN; j += 4)
                *reinterpret_cast<float4*>(&bw[j]) =
                    *reinterpret_cast<const float4*>(&Ws[k][tx * TN + j]);
            unsigned long long b2[TN];
            #pragma unroll
            for (int j = 0; j < TN; j++) b2[j] = dup_f32(bw[j]);

            #pragma unroll
            for (int rp = 0; rp < 4; rp++)
                #pragma unroll
                for (int j = 0; j < TN; j++)
                    ffma2(acc2[rp][j], a2[rp], b2[j]);
        }
        __syncthreads();
    }

    // ---- fused epilogue ----
    float bb[TN];
    #pragma unroll
    for (int j = 0; j < TN; j++) bb[j] = bias[tx * TN + j];

    #pragma unroll
    for (int rp = 0; rp < 4; rp++) {
        float h0[TN], h1[TN];
        #pragma unroll
        for (int j = 0; j < TN; j++) unpack2(acc2[rp][j], h0[j], h1[j]);

        int row0 = rowBase + ty * 8 + 2 * rp;
        #pragma unroll
        for (int half = 0; half < 2; half++) {
            int row = row0 + half;
            if (row >= N) continue;
            float* h = half ? h1 : h0;
            float di = g_dinv[row];
            float s = di * di;
            float o4[8];
            #pragma unroll
            for (int j = 0; j < TN; j++) o4[j] = fmaf(h[j], s, bb[j]);
            size_t base = (size_t)row * BN + tx * TN;
            #pragma unroll
            for (int j = 0; j < TN; j += 4) {
                *reinterpret_cast<float4*>(&g_H[base + j]) =
                    *reinterpret_cast<const float4*>(&h[j]);
                *reinterpret_cast<float4*>(&OUT[base + j]) =
                    *reinterpret_cast<const float4*>(&o4[j]);
            }
        }
    }
}

// ---------------------------------------------------------------------------
// CSR aggregation: one warp per dst node, segmented reduction over in-edges.
// OUT[dst] += sum_e H[src_e] * norm_e   (OUT pre-initialized with self+bias)
// ---------------------------------------------------------------------------
template <int F, bool TO_GB>
__global__ void aggregate_kernel(float* __restrict__ outp, int N) {
    constexpr int LANES = F / 4;
    int warp = (blockIdx.x * blockDim.x + threadIdx.x) >> 5;
    int lane = threadIdx.x & 31;
    if (warp >= N) return;

    int e = g_rowptr[warp];
    int end = g_rowptr[warp + 1];

    const float4* __restrict__ H4 = reinterpret_cast<const float4*>(g_H);
    float4 acc = make_float4(0.f, 0.f, 0.f, 0.f);

    for (; e + 1 < end; e += 2) {
        int s0 = g_src[e], s1 = g_src[e + 1];
        float n0 = g_enorm[e], n1 = g_enorm[e + 1];
        if (lane < LANES) {
            float4 v0 = H4[(size_t)s0 * LANES + lane];
            float4 v1 = H4[(size_t)s1 * LANES + lane];
            acc.x = fmaf(v0.x, n0, fmaf(v1.x, n1, acc.x));
            acc.y = fmaf(v0.y, n0, fmaf(v1.y, n1, acc.y));
            acc.z = fmaf(v0.z, n0, fmaf(v1.z, n1, acc.z));
            acc.w = fmaf(v0.w, n0, fmaf(v1.w, n1, acc.w));
        }
    }
    if (e < end) {
        int s0 = g_src[e];
        float n0 = g_enorm[e];
        if (lane < LANES) {
            float4 v0 = H4[(size_t)s0 * LANES + lane];
            acc.x = fmaf(v0.x, n0, acc.x);
            acc.y = fmaf(v0.y, n0, acc.y);
            acc.z = fmaf(v0.z, n0, acc.z);
            acc.w = fmaf(v0.w, n0, acc.w);
        }
    }

    if (lane < LANES) {
        float4* o = (TO_GB ? reinterpret_cast<float4*>(g_B)
                           : reinterpret_cast<float4*>(outp)) +
                    (size_t)warp * LANES + lane;
        float4 cur = *o;
        cur.x += acc.x; cur.y += acc.y; cur.z += acc.z; cur.w += acc.w;
        *o = cur;
    }
}

// ---------------------------------------------------------------------------
// Launch
// ---------------------------------------------------------------------------
extern "C" void kernel_launch(void* const* d_in, const int* in_sizes, int n_in,
                              void* d_out, int out_size) {
    const float* x  = (const float*)d_in[0];
    const void*  ei = d_in[1];
    const float* W1 = (const float*)d_in[2];
    const float* b1 = (const float*)d_in[3];
    const float* W2 = (const float*)d_in[4];
    const float* b2 = (const float*)d_in[5];
    const float* W3 = (const float*)d_in[6];
    const float* b3 = (const float*)d_in[7];
    float* out = (float*)d_out;

    const int N = in_sizes[0] / 128;
    const int E = in_sizes[1] / 2;
    const int T = 256;

    // ---- prep: CSR by dst + norms (shared across layers) ----
    detect_dtype_kernel<<<1, 32>>>(ei, E, N);
    zero_cnt_kernel<<<(N + T - 1) / T, T>>>(N);
    count_kernel<<<(E + T - 1) / T, T>>>(ei, E);
    dinv_kernel<<<(N + T - 1) / T, T>>>(N);
    scan_kernel<<<1, 1024>>>(N);
    fill_kernel<<<(E + T - 1) / T, T>>>(ei, E);

    const int gemmBlocks = (N + 127) / 128;
    const int aggBlocks = (N * 32 + T - 1) / T;

    // ---- layer 1 ----
    gemm_fused_kernel<128, false, false, true><<<gemmBlocks, 256>>>(x, W1, b1, nullptr, N);
    aggregate_kernel<128, true><<<aggBlocks, T>>>(nullptr, N);

    // ---- layer 2 (relu fused into X load) ----
    gemm_fused_kernel<128, true, true, true><<<gemmBlocks, 256>>>(nullptr, W2, b2, nullptr, N);
    aggregate_kernel<128, true><<<aggBlocks, T>>>(nullptr, N);

    // ---- layer 3 -> d_out ----
    gemm_fused_kernel<64, true, true, false><<<gemmBlocks, 256>>>(nullptr, W3, b3, out, N);
    aggregate_kernel<64, false><<<aggBlocks, T>>>(out, N);
}

// round 7
// speedup vs baseline: 1.8298x; 1.1376x over previous
#include <cuda_runtime.h>

// ---------------------------------------------------------------------------
// 3-layer GCN, symmetric norm D^{-1/2}(A+I)D^{-1/2}, self-loops.
// N=50000, E=640000, features 128 -> 128 -> 128 -> 64.
// R7: multi-block scan prep, zero-pass elimination (atomicSub cursor),
// self-loop+bias fused into CSR aggregate, 4-edge unrolled gather.
// ---------------------------------------------------------------------------

#define MAX_N 50048
#define MAX_E 640000
#define SCAN_CHUNK 1024

__device__ __align__(16) float g_H[MAX_N * 128];    // H = X @ W
__device__ __align__(16) float g_B[MAX_N * 128];    // layer output
__device__ __align__(16) float g_enorm[MAX_E];      // norm per SORTED edge
__device__ __align__(16) int   g_src[MAX_E];        // src per SORTED edge
__device__ int   g_rowptr[MAX_N + 1];
__device__ int   g_cnt[MAX_N];                      // ZERO between replays (invariant)
__device__ int   g_bsum[(MAX_N + SCAN_CHUNK - 1) / SCAN_CHUNK];
__device__ float g_dinv[MAX_N];
__device__ int   g_is64;

// ---------------------------------------------------------------------------
// f32x2 helpers
// ---------------------------------------------------------------------------
__device__ __forceinline__ unsigned long long dup_f32(float w) {
    unsigned long long r;
    asm("mov.b64 %0, {%1, %1};" : "=l"(r) : "f"(w));
    return r;
}
__device__ __forceinline__ void ffma2(unsigned long long& d,
                                      unsigned long long a,
                                      unsigned long long b) {
    asm("fma.rn.f32x2 %0, %1, %2, %0;" : "+l"(d) : "l"(a), "l"(b));
}
__device__ __forceinline__ void unpack2(unsigned long long v, float& lo, float& hi) {
    asm("mov.b64 {%0, %1}, %2;" : "=f"(lo), "=f"(hi) : "l"(v));
}

// ---------------------------------------------------------------------------
// Prep
// ---------------------------------------------------------------------------
__global__ void detect_dtype_kernel(const void* __restrict__ ei, int E, int N) {
    if (threadIdx.x == 0 && blockIdx.x == 0) {
        const long long* p = (const long long*)ei;
        int ok = 1;
        int take = E < 128 ? E : 128;
        for (int i = 0; i < take; i++) {
            long long v = p[i];
            if (v < 0 || v >= (long long)N) { ok = 0; break; }
        }
        g_is64 = ok;
    }
}

__device__ __forceinline__ void decode_edge(const void* ei, int E, int e,
                                            int& s, int& d) {
    if (g_is64) {
        const long long* p = (const long long*)ei;
        s = (int)p[e];
        d = (int)p[E + e];
    } else {
        const int* p = (const int*)ei;
        s = p[e];
        d = p[E + e];
    }
}

// In-degree count. Relies on g_cnt == 0 (initial state / restored by fill).
__global__ void count_kernel(const void* __restrict__ ei, int E) {
    int e = blockIdx.x * blockDim.x + threadIdx.x;
    if (e >= E) return;
    int d;
    if (g_is64) d = (int)((const long long*)ei)[E + e];
    else        d = ((const int*)ei)[E + e];
    atomicAdd(&g_cnt[d], 1);
}

// Scan phase 1: per-block (1024 elems) exclusive scan + block sum + dinv.
__global__ void scan1_kernel(int n) {
    __shared__ int warpsum[8];
    const int tid = threadIdx.x, lane = tid & 31, wid = tid >> 5;
    const int base = blockIdx.x * SCAN_CHUNK + tid * 4;

    int v[4] = {0, 0, 0, 0};
    if (base + 3 < n) {
        *reinterpret_cast<int4*>(v) = *reinterpret_cast<const int4*>(&g_cnt[base]);
    } else {
        for (int j = 0; j < 4; j++) if (base + j < n) v[j] = g_cnt[base + j];
    }
    #pragma unroll
    for (int j = 0; j < 4; j++)
        if (base + j < n) g_dinv[base + j] = rsqrtf((float)v[j] + 1.0f);

    int t0 = v[0], t1 = t0 + v[1], t2 = t1 + v[2], t3 = t2 + v[3];
    int x = t3;
    #pragma unroll
    for (int off = 1; off < 32; off <<= 1) {
        int t = __shfl_up_sync(0xffffffffu, x, off);
        if (lane >= off) x += t;
    }
    if (lane == 31) warpsum[wid] = x;
    __syncthreads();
    if (wid == 0 && lane < 8) {
        int w = warpsum[lane];
        #pragma unroll
        for (int off = 1; off < 8; off <<= 1) {
            int t = __shfl_up_sync(0xffu, w, off);
            if (lane >= off) w += t;
        }
        warpsum[lane] = w;
    }
    __syncthreads();

    int off = (x - t3) + (wid > 0 ? warpsum[wid - 1] : 0);  // exclusive base
    int pre[4] = {0, t0, t1, t2};
    #pragma unroll
    for (int j = 0; j < 4; j++)
        if (base + j < n) g_rowptr[base + j] = off + pre[j];

    if (tid == 0) g_bsum[blockIdx.x] = 0;  // will be set by last warp's total
    __syncthreads();
    if (tid == 255) g_bsum[blockIdx.x] = warpsum[7];
}

// Scan phase 2: serial exclusive scan of block sums (tiny), writes rowptr[n].
__global__ void scan2_kernel(int nb, int n) {
    if (threadIdx.x == 0 && blockIdx.x == 0) {
        int run = 0;
        for (int b = 0; b < nb; b++) {
            int t = g_bsum[b];
            g_bsum[b] = run;
            run += t;
        }
        g_rowptr[n] = run;
    }
}

// Scan phase 3: add block offsets.
__global__ void scan3_kernel(int n) {
    int i = blockIdx.x * blockDim.x + threadIdx.x;
    if (i < n) g_rowptr[i] += g_bsum[i >> 10];
}

// Fill sorted edge arrays. atomicSub restores g_cnt to 0 (invariant).
__global__ void fill_kernel(const void* __restrict__ ei, int E) {
    int e = blockIdx.x * blockDim.x + threadIdx.x;
    if (e >= E) return;
    int s, d;
    decode_edge(ei, E, e, s, d);
    int pos = g_rowptr[d] + atomicSub(&g_cnt[d], 1) - 1;
    g_src[pos] = s;
    g_enorm[pos] = g_dinv[s] * g_dinv[d];
}

// ---------------------------------------------------------------------------
// FFMA2 register-tiled SGEMM: g_H = X @ W  (raw pre-aggregation only)
// BM=128, BK=16, BN=FOUT. 256 threads; 8 rows (4 f32x2 pairs) x TN cols.
// ---------------------------------------------------------------------------
template <int BN, bool RELU, bool FROM_GB>
__global__ __launch_bounds__(256, 2)
void gemm_kernel(const float* __restrict__ Xin,
                 const float* __restrict__ W, int N) {
    constexpr int BM = 128, BK = 16;
    constexpr int TN = BN / 16;
    constexpr int WI = (BK * BN) / 1024;

    __shared__ float Xs[BK][BM + 4];
    __shared__ float Ws[BK][BN];

    const float* __restrict__ X = FROM_GB ? (const float*)g_B : Xin;

    const int tid = threadIdx.x;
    const int tx = tid & 15;
    const int ty = tid >> 4;
    const int rowBase = blockIdx.x * BM;

    unsigned long long acc2[4][TN];
    #pragma unroll
    for (int i = 0; i < 4; i++)
        #pragma unroll
        for (int j = 0; j < TN; j++) acc2[i][j] = 0ull;

    for (int kc = 0; kc < 128; kc += BK) {
        #pragma unroll
        for (int i = 0; i < 2; i++) {
            int j = tid + 256 * i;
            int row = j >> 2;
            int kq = j & 3;
            int r = rowBase + row;
            float4 v = make_float4(0.f, 0.f, 0.f, 0.f);
            if (r < N)
                v = *reinterpret_cast<const float4*>(&X[(size_t)r * 128 + kc + kq * 4]);
            if (RELU) {
                v.x = fmaxf(v.x, 0.f); v.y = fmaxf(v.y, 0.f);
                v.z = fmaxf(v.z, 0.f); v.w = fmaxf(v.w, 0.f);
            }
            Xs[kq * 4 + 0][row] = v.x;
            Xs[kq * 4 + 1][row] = v.y;
            Xs[kq * 4 + 2][row] = v.z;
            Xs[kq * 4 + 3][row] = v.w;
        }
        #pragma unroll
        for (int i = 0; i < WI; i++) {
            int j = tid + 256 * i;
            int kk = j / (BN / 4);
            int cc = j % (BN / 4);
            *reinterpret_cast<float4*>(&Ws[kk][cc * 4]) =
                *reinterpret_cast<const float4*>(&W[(size_t)(kc + kk) * BN + cc * 4]);
        }
        __syncthreads();

        #pragma unroll
        for (int k = 0; k < BK; k++) {
            const ulonglong2* ap =
                reinterpret_cast<const ulonglong2*>(&Xs[k][ty * 8]);
            ulonglong2 a01 = ap[0];
            ulonglong2 a23 = ap[1];
            unsigned long long a2[4] = {a01.x, a01.y, a23.x, a23.y};

            float bw[TN];
            #pragma unroll
            for (int j = 0; j < TN; j += 4)
                *reinterpret_cast<float4*>(&bw[j]) =
                    *reinterpret_cast<const float4*>(&Ws[k][tx * TN + j]);
            unsigned long long b2[TN];
            #pragma unroll
            for (int j = 0; j < TN; j++) b2[j] = dup_f32(bw[j]);

            #pragma unroll
            for (int rp = 0; rp < 4; rp++)
                #pragma unroll
                for (int j = 0; j < TN; j++)
                    ffma2(acc2[rp][j], a2[rp], b2[j]);
        }
        __syncthreads();
    }

    #pragma unroll
    for (int rp = 0; rp < 4; rp++) {
        float h0[TN], h1[TN];
        #pragma unroll
        for (int j = 0; j < TN; j++) unpack2(acc2[rp][j], h0[j], h1[j]);
        int row0 = rowBase + ty * 8 + 2 * rp;
        #pragma unroll
        for (int half = 0; half < 2; half++) {
            int row = row0 + half;
            if (row >= N) continue;
            float* h = half ? h1 : h0;
            size_t base = (size_t)row * BN + tx * TN;
            #pragma unroll
            for (int j = 0; j < TN; j += 4)
                *reinterpret_cast<float4*>(&g_H[base + j]) =
                    *reinterpret_cast<const float4*>(&h[j]);
        }
    }
}

// ---------------------------------------------------------------------------
// CSR aggregation, self-loop + bias fused, pure write:
//   OUT[d] = sum_e H[src_e]*norm_e + H[d]*dinv[d]^2 + bias
// One warp per dst node; 4-edge unroll for MLP.
// ---------------------------------------------------------------------------
template <int F, bool TO_GB>
__global__ void aggregate_kernel(const float* __restrict__ bias,
                                 float* __restrict__ outp, int N) {
    constexpr int LANES = F / 4;
    int warp = (blockIdx.x * blockDim.x + threadIdx.x) >> 5;
    int lane = threadIdx.x & 31;
    if (warp >= N) return;

    int e = g_rowptr[warp];
    const int end = g_rowptr[warp + 1];

    const float4* __restrict__ H4 = reinterpret_cast<const float4*>(g_H);
    float4 acc = make_float4(0.f, 0.f, 0.f, 0.f);

    // self-loop seed: H[d]*dinv^2 + bias
    if (lane < LANES) {
        float di = g_dinv[warp];
        float s = di * di;
        float4 hd = H4[(size_t)warp * LANES + lane];
        float4 bb = reinterpret_cast<const float4*>(bias)[lane];
        acc.x = fmaf(hd.x, s, bb.x);
        acc.y = fmaf(hd.y, s, bb.y);
        acc.z = fmaf(hd.z, s, bb.z);
        acc.w = fmaf(hd.w, s, bb.w);
    }

    for (; e + 3 < end; e += 4) {
        int s0 = g_src[e], s1 = g_src[e + 1], s2 = g_src[e + 2], s3 = g_src[e + 3];
        float n0 = g_enorm[e], n1 = g_enorm[e + 1];
        float n2 = g_enorm[e + 2], n3 = g_enorm[e + 3];
        if (lane < LANES) {
            float4 v0 = H4[(size_t)s0 * LANES + lane];
            float4 v1 = H4[(size_t)s1 * LANES + lane];
            float4 v2 = H4[(size_t)s2 * LANES + lane];
            float4 v3 = H4[(size_t)s3 * LANES + lane];
            acc.x += v0.x * n0 + v1.x * n1 + v2.x * n2 + v3.x * n3;
            acc.y += v0.y * n0 + v1.y * n1 + v2.y * n2 + v3.y * n3;
            acc.z += v0.z * n0 + v1.z * n1 + v2.z * n2 + v3.z * n3;
            acc.w += v0.w * n0 + v1.w * n1 + v2.w * n2 + v3.w * n3;
        }
    }
    for (; e < end; e++) {
        int s0 = g_src[e];
        float n0 = g_enorm[e];
        if (lane < LANES) {
            float4 v0 = H4[(size_t)s0 * LANES + lane];
            acc.x = fmaf(v0.x, n0, acc.x);
            acc.y = fmaf(v0.y, n0, acc.y);
            acc.z = fmaf(v0.z, n0, acc.z);
            acc.w = fmaf(v0.w, n0, acc.w);
        }
    }

    if (lane < LANES) {
        float4* o = (TO_GB ? reinterpret_cast<float4*>(g_B)
                           : reinterpret_cast<float4*>(outp)) +
                    (size_t)warp * LANES + lane;
        *o = acc;
    }
}

// ---------------------------------------------------------------------------
// Launch
// ---------------------------------------------------------------------------
extern "C" void kernel_launch(void* const* d_in, const int* in_sizes, int n_in,
                              void* d_out, int out_size) {
    const float* x  = (const float*)d_in[0];
    const void*  ei = d_in[1];
    const float* W1 = (const float*)d_in[2];
    const float* b1 = (const float*)d_in[3];
    const float* W2 = (const float*)d_in[4];
    const float* b2 = (const float*)d_in[5];
    const float* W3 = (const float*)d_in[6];
    const float* b3 = (const float*)d_in[7];
    float* out = (float*)d_out;

    const int N = in_sizes[0] / 128;
    const int E = in_sizes[1] / 2;
    const int T = 256;
    const int nb = (N + SCAN_CHUNK - 1) / SCAN_CHUNK;

    // ---- prep (g_cnt starts zero: initial state / restored by fill) ----
    detect_dtype_kernel<<<1, 32>>>(ei, E, N);
    count_kernel<<<(E + T - 1) / T, T>>>(ei, E);
    scan1_kernel<<<nb, 256>>>(N);
    scan2_kernel<<<1, 32>>>(nb, N);
    scan3_kernel<<<(N + T - 1) / T, T>>>(N);
    fill_kernel<<<(E + T - 1) / T, T>>>(ei, E);

    const int gemmBlocks = (N + 127) / 128;
    const int aggBlocks = (N * 32 + T - 1) / T;

    // ---- layer 1 ----
    gemm_kernel<128, false, false><<<gemmBlocks, 256>>>(x, W1, N);
    aggregate_kernel<128, true><<<aggBlocks, T>>>(b1, nullptr, N);

    // ---- layer 2 (relu fused into X load) ----
    gemm_kernel<128, true, true><<<gemmBlocks, 256>>>(nullptr, W2, N);
    aggregate_kernel<128, true><<<aggBlocks, T>>>(b2, nullptr, N);

    // ---- layer 3 -> d_out ----
    gemm_kernel<64, true, true><<<gemmBlocks, 256>>>(nullptr, W3, N);
    aggregate_kernel<64, false><<<aggBlocks, T>>>(b3, out, N);
}

// round 8
// speedup vs baseline: 1.9156x; 1.0469x over previous
#include <cuda_runtime.h>

// ---------------------------------------------------------------------------
// 3-layer GCN, symmetric norm D^{-1/2}(A+I)D^{-1/2}, self-loops.
// N=50000, E=640000, features 128 -> 128 -> 128 -> 64.
// R8: parallel scan2/detect, 8-edge-unrolled aggregate, software-pipelined
// FFMA2 GEMM.
// ---------------------------------------------------------------------------

#define MAX_N 50048
#define MAX_E 640000
#define SCAN_CHUNK 1024

__device__ __align__(16) float g_H[MAX_N * 128];
__device__ __align__(16) float g_B[MAX_N * 128];
__device__ __align__(16) float g_enorm[MAX_E];
__device__ __align__(16) int   g_src[MAX_E];
__device__ int   g_rowptr[MAX_N + 1];
__device__ int   g_cnt[MAX_N];                      // ZERO between replays
__device__ int   g_bsum[(MAX_N + SCAN_CHUNK - 1) / SCAN_CHUNK];
__device__ float g_dinv[MAX_N];
__device__ int   g_is64;

// ---------------------------------------------------------------------------
// f32x2 helpers
// ---------------------------------------------------------------------------
__device__ __forceinline__ unsigned long long dup_f32(float w) {
    unsigned long long r;
    asm("mov.b64 %0, {%1, %1};" : "=l"(r) : "f"(w));
    return r;
}
__device__ __forceinline__ void ffma2(unsigned long long& d,
                                      unsigned long long a,
                                      unsigned long long b) {
    asm("fma.rn.f32x2 %0, %1, %2, %0;" : "+l"(d) : "l"(a), "l"(b));
}
__device__ __forceinline__ void unpack2(unsigned long long v, float& lo, float& hi) {
    asm("mov.b64 {%0, %1}, %2;" : "=f"(lo), "=f"(hi) : "l"(v));
}

// ---------------------------------------------------------------------------
// Prep
// ---------------------------------------------------------------------------
__global__ void detect_dtype_kernel(const void* __restrict__ ei, int E, int N) {
    // 32 threads x 4 samples; int64 data in-range ==> is64.
    int tid = threadIdx.x;
    const long long* p = (const long long*)ei;
    int take = E < 128 ? E : 128;
    int bad = 0;
    for (int j = tid * 4; j < tid * 4 + 4; j++) {
        if (j < take) {
            long long v = p[j];
            if (v < 0 || v >= (long long)N) bad = 1;
        }
    }
    unsigned m = __ballot_sync(0xffffffffu, bad);
    if (tid == 0) g_is64 = (m == 0u);
}

__device__ __forceinline__ void decode_edge(const void* ei, int E, int e,
                                            int& s, int& d) {
    if (g_is64) {
        const long long* p = (const long long*)ei;
        s = (int)p[e];
        d = (int)p[E + e];
    } else {
        const int* p = (const int*)ei;
        s = p[e];
        d = p[E + e];
    }
}

__global__ void count_kernel(const void* __restrict__ ei, int E) {
    int e = blockIdx.x * blockDim.x + threadIdx.x;
    if (e >= E) return;
    int d;
    if (g_is64) d = (int)((const long long*)ei)[E + e];
    else        d = ((const int*)ei)[E + e];
    atomicAdd(&g_cnt[d], 1);
}

// Scan phase 1: per-block (1024 elems) exclusive scan + block sum + dinv.
__global__ void scan1_kernel(int n) {
    __shared__ int warpsum[8];
    const int tid = threadIdx.x, lane = tid & 31, wid = tid >> 5;
    const int base = blockIdx.x * SCAN_CHUNK + tid * 4;

    int v[4] = {0, 0, 0, 0};
    if (base + 3 < n) {
        *reinterpret_cast<int4*>(v) = *reinterpret_cast<const int4*>(&g_cnt[base]);
    } else {
        for (int j = 0; j < 4; j++) if (base + j < n) v[j] = g_cnt[base + j];
    }
    #pragma unroll
    for (int j = 0; j < 4; j++)
        if (base + j < n) g_dinv[base + j] = rsqrtf((float)v[j] + 1.0f);

    int t0 = v[0], t1 = t0 + v[1], t2 = t1 + v[2], t3 = t2 + v[3];
    int x = t3;
    #pragma unroll
    for (int off = 1; off < 32; off <<= 1) {
        int t = __shfl_up_sync(0xffffffffu, x, off);
        if (lane >= off) x += t;
    }
    if (lane == 31) warpsum[wid] = x;
    __syncthreads();
    if (wid == 0 && lane < 8) {
        int w = warpsum[lane];
        #pragma unroll
        for (int off = 1; off < 8; off <<= 1) {
            int t = __shfl_up_sync(0xffu, w, off);
            if (lane >= off) w += t;
        }
        warpsum[lane] = w;
    }
    __syncthreads();

    int off = (x - t3) + (wid > 0 ? warpsum[wid - 1] : 0);
    int pre[4] = {0, t0, t1, t2};
    #pragma unroll
    for (int j = 0; j < 4; j++)
        if (base + j < n) g_rowptr[base + j] = off + pre[j];

    if (tid == 255) g_bsum[blockIdx.x] = warpsum[7];
}

// Scan phase 2: 64-thread parallel exclusive scan of <=64 block sums.
__global__ void scan2_kernel(int nb, int n) {
    __shared__ int ws[2];
    int tid = threadIdx.x, lane = tid & 31, wid = tid >> 5;
    int v = (tid < nb) ? g_bsum[tid] : 0;
    int x = v;
    #pragma unroll
    for (int off = 1; off < 32; off <<= 1) {
        int t = __shfl_up_sync(0xffffffffu, x, off);
        if (lane >= off) x += t;
    }
    if (lane == 31) ws[wid] = x;
    __syncthreads();
    if (wid == 1) x += ws[0];
    if (tid < nb) g_bsum[tid] = x - v;        // exclusive
    if (tid == nb - 1) g_rowptr[n] = x;       // total
}

__global__ void scan3_kernel(int n) {
    int i = blockIdx.x * blockDim.x + threadIdx.x;
    if (i < n) g_rowptr[i] += g_bsum[i >> 10];
}

// Fill sorted edge arrays. atomicSub restores g_cnt to 0 (invariant).
__global__ void fill_kernel(const void* __restrict__ ei, int E) {
    int e = blockIdx.x * blockDim.x + threadIdx.x;
    if (e >= E) return;
    int s, d;
    decode_edge(ei, E, e, s, d);
    int pos = g_rowptr[d] + atomicSub(&g_cnt[d], 1) - 1;
    g_src[pos] = s;
    g_enorm[pos] = g_dinv[s] * g_dinv[d];
}

// ---------------------------------------------------------------------------
// FFMA2 register-tiled SGEMM, software-pipelined tiles: g_H = X @ W
// BM=128, BK=16, BN=FOUT. 256 threads; 8 rows (4 f32x2 pairs) x TN cols.
// ---------------------------------------------------------------------------
template <int BN, bool RELU, bool FROM_GB>
__global__ __launch_bounds__(256, 2)
void gemm_kernel(const float* __restrict__ Xin,
                 const float* __restrict__ W, int N) {
    constexpr int BM = 128, BK = 16;
    constexpr int TN = BN / 16;
    constexpr int WI = (BK * BN) / 1024;      // 2 or 1 float4 per thread

    __shared__ float Xs[BK][BM + 4];
    __shared__ float Ws[BK][BN];

    const float* __restrict__ X = FROM_GB ? (const float*)g_B : Xin;

    const int tid = threadIdx.x;
    const int tx = tid & 15;
    const int ty = tid >> 4;
    const int rowBase = blockIdx.x * BM;

    // addressing for loads (constant across tiles)
    const int xrow0 = tid >> 2, xkq0 = tid & 3;             // slot tid
    const int xrow1 = (tid + 256) >> 2, xkq1 = (tid + 256) & 3;
    const int r0 = rowBase + xrow0, r1 = rowBase + xrow1;

    float4 xr[2], wr[2];

    auto load_tile = [&](int kc) {
        xr[0] = make_float4(0.f, 0.f, 0.f, 0.f);
        xr[1] = make_float4(0.f, 0.f, 0.f, 0.f);
        if (r0 < N)
            xr[0] = *reinterpret_cast<const float4*>(&X[(size_t)r0 * 128 + kc + xkq0 * 4]);
        if (r1 < N)
            xr[1] = *reinterpret_cast<const float4*>(&X[(size_t)r1 * 128 + kc + xkq1 * 4]);
        if (RELU) {
            xr[0].x = fmaxf(xr[0].x, 0.f); xr[0].y = fmaxf(xr[0].y, 0.f);
            xr[0].z = fmaxf(xr[0].z, 0.f); xr[0].w = fmaxf(xr[0].w, 0.f);
            xr[1].x = fmaxf(xr[1].x, 0.f); xr[1].y = fmaxf(xr[1].y, 0.f);
            xr[1].z = fmaxf(xr[1].z, 0.f); xr[1].w = fmaxf(xr[1].w, 0.f);
        }
        #pragma unroll
        for (int i = 0; i < WI; i++) {
            int j = tid + 256 * i;
            int kk = j / (BN / 4);
            int cc = j % (BN / 4);
            wr[i] = *reinterpret_cast<const float4*>(&W[(size_t)(kc + kk) * BN + cc * 4]);
        }
    };
    auto store_tile = [&]() {
        Xs[xkq0 * 4 + 0][xrow0] = xr[0].x;
        Xs[xkq0 * 4 + 1][xrow0] = xr[0].y;
        Xs[xkq0 * 4 + 2][xrow0] = xr[0].z;
        Xs[xkq0 * 4 + 3][xrow0] = xr[0].w;
        Xs[xkq1 * 4 + 0][xrow1] = xr[1].x;
        Xs[xkq1 * 4 + 1][xrow1] = xr[1].y;
        Xs[xkq1 * 4 + 2][xrow1] = xr[1].z;
        Xs[xkq1 * 4 + 3][xrow1] = xr[1].w;
        #pragma unroll
        for (int i = 0; i < WI; i++) {
            int j = tid + 256 * i;
            int kk = j / (BN / 4);
            int cc = j % (BN / 4);
            *reinterpret_cast<float4*>(&Ws[kk][cc * 4]) = wr[i];
        }
    };

    unsigned long long acc2[4][TN];
    #pragma unroll
    for (int i = 0; i < 4; i++)
        #pragma unroll
        for (int j = 0; j < TN; j++) acc2[i][j] = 0ull;

    load_tile(0);
    store_tile();
    __syncthreads();

    for (int t = 0; t < 128 / BK; t++) {
        if (t + 1 < 128 / BK) load_tile((t + 1) * BK);  // in flight over compute

        #pragma unroll
        for (int k = 0; k < BK; k++) {
            const ulonglong2* ap =
                reinterpret_cast<const ulonglong2*>(&Xs[k][ty * 8]);
            ulonglong2 a01 = ap[0];
            ulonglong2 a23 = ap[1];
            unsigned long long a2[4] = {a01.x, a01.y, a23.x, a23.y};

            float bw[TN];
            #pragma unroll
            for (int j = 0; j < TN; j += 4)
                *reinterpret_cast<float4*>(&bw[j]) =
                    *reinterpret_cast<const float4*>(&Ws[k][tx * TN + j]);
            unsigned long long b2[TN];
            #pragma unroll
            for (int j = 0; j < TN; j++) b2[j] = dup_f32(bw[j]);

            #pragma unroll
            for (int rp = 0; rp < 4; rp++)
                #pragma unroll
                for (int j = 0; j < TN; j++)
                    ffma2(acc2[rp][j], a2[rp], b2[j]);
        }
        __syncthreads();
        if (t + 1 < 128 / BK) {
            store_tile();
            __syncthreads();
        }
    }

    #pragma unroll
    for (int rp = 0; rp < 4; rp++) {
        float h0[TN], h1[TN];
        #pragma unroll
        for (int j = 0; j < TN; j++) unpack2(acc2[rp][j], h0[j], h1[j]);
        int row0 = rowBase + ty * 8 + 2 * rp;
        #pragma unroll
        for (int half = 0; half < 2; half++) {
            int row = row0 + half;
            if (row >= N) continue;
            float* h = half ? h1 : h0;
            size_t base = (size_t)row * BN + tx * TN;
            #pragma unroll
            for (int j = 0; j < TN; j += 4)
                *reinterpret_cast<float4*>(&g_H[base + j]) =
                    *reinterpret_cast<const float4*>(&h[j]);
        }
    }
}

// ---------------------------------------------------------------------------
// CSR aggregation, self-loop + bias fused, 8-edge unroll, pure write:
//   OUT[d] = sum_e H[src_e]*norm_e + H[d]*dinv[d]^2 + bias
// ---------------------------------------------------------------------------
template <int F, bool TO_GB>
__global__ void aggregate_kernel(const float* __restrict__ bias,
                                 float* __restrict__ outp, int N) {
    constexpr int LANES = F / 4;
    int warp = (blockIdx.x * blockDim.x + threadIdx.x) >> 5;
    int lane = threadIdx.x & 31;
    if (warp >= N) return;

    int e = g_rowptr[warp];
    const int end = g_rowptr[warp + 1];

    const float4* __restrict__ H4 = reinterpret_cast<const float4*>(g_H);
    float4 acc = make_float4(0.f, 0.f, 0.f, 0.f);

    if (lane < LANES) {
        float di = g_dinv[warp];
        float s = di * di;
        float4 hd = H4[(size_t)warp * LANES + lane];
        float4 bb = reinterpret_cast<const float4*>(bias)[lane];
        acc.x = fmaf(hd.x, s, bb.x);
        acc.y = fmaf(hd.y, s, bb.y);
        acc.z = fmaf(hd.z, s, bb.z);
        acc.w = fmaf(hd.w, s, bb.w);
    }

    for (; e + 7 < end; e += 8) {
        int   si[8];
        float ni[8];
        #pragma unroll
        for (int j = 0; j < 8; j++) { si[j] = g_src[e + j]; ni[j] = g_enorm[e + j]; }
        if (lane < LANES) {
            float4 v[8];
            #pragma unroll
            for (int j = 0; j < 8; j++) v[j] = H4[(size_t)si[j] * LANES + lane];
            #pragma unroll
            for (int j = 0; j < 8; j++) {
                acc.x = fmaf(v[j].x, ni[j], acc.x);
                acc.y = fmaf(v[j].y, ni[j], acc.y);
                acc.z = fmaf(v[j].z, ni[j], acc.z);
                acc.w = fmaf(v[j].w, ni[j], acc.w);
            }
        }
    }
    for (; e + 3 < end; e += 4) {
        int s0 = g_src[e], s1 = g_src[e + 1], s2 = g_src[e + 2], s3 = g_src[e + 3];
        float n0 = g_enorm[e], n1 = g_enorm[e + 1];
        float n2 = g_enorm[e + 2], n3 = g_enorm[e + 3];
        if (lane < LANES) {
            float4 v0 = H4[(size_t)s0 * LANES + lane];
            float4 v1 = H4[(size_t)s1 * LANES + lane];
            float4 v2 = H4[(size_t)s2 * LANES + lane];
            float4 v3 = H4[(size_t)s3 * LANES + lane];
            acc.x += v0.x * n0 + v1.x * n1 + v2.x * n2 + v3.x * n3;
            acc.y += v0.y * n0 + v1.y * n1 + v2.y * n2 + v3.y * n3;
            acc.z += v0.z * n0 + v1.z * n1 + v2.z * n2 + v3.z * n3;
            acc.w += v0.w * n0 + v1.w * n1 + v2.w * n2 + v3.w * n3;
        }
    }
    for (; e < end; e++) {
        int s0 = g_src[e];
        float n0 = g_enorm[e];
        if (lane < LANES) {
            float4 v0 = H4[(size_t)s0 * LANES + lane];
            acc.x = fmaf(v0.x, n0, acc.x);
            acc.y = fmaf(v0.y, n0, acc.y);
            acc.z = fmaf(v0.z, n0, acc.z);
            acc.w = fmaf(v0.w, n0, acc.w);
        }
    }

    if (lane < LANES) {
        float4* o = (TO_GB ? reinterpret_cast<float4*>(g_B)
                           : reinterpret_cast<float4*>(outp)) +
                    (size_t)warp * LANES + lane;
        *o = acc;
    }
}

// ---------------------------------------------------------------------------
// Launch
// ---------------------------------------------------------------------------
extern "C" void kernel_launch(void* const* d_in, const int* in_sizes, int n_in,
                              void* d_out, int out_size) {
    const float* x  = (const float*)d_in[0];
    const void*  ei = d_in[1];
    const float* W1 = (const float*)d_in[2];
    const float* b1 = (const float*)d_in[3];
    const float* W2 = (const float*)d_in[4];
    const float* b2 = (const float*)d_in[5];
    const float* W3 = (const float*)d_in[6];
    const float* b3 = (const float*)d_in[7];
    float* out = (float*)d_out;

    const int N = in_sizes[0] / 128;
    const int E = in_sizes[1] / 2;
    const int T = 256;
    const int nb = (N + SCAN_CHUNK - 1) / SCAN_CHUNK;

    detect_dtype_kernel<<<1, 32>>>(ei, E, N);
    count_kernel<<<(E + T - 1) / T, T>>>(ei, E);
    scan1_kernel<<<nb, 256>>>(N);
    scan2_kernel<<<1, 64>>>(nb, N);
    scan3_kernel<<<(N + T - 1) / T, T>>>(N);
    fill_kernel<<<(E + T - 1) / T, T>>>(ei, E);

    const int gemmBlocks = (N + 127) / 128;
    const int aggBlocks = (N * 32 + T - 1) / T;

    gemm_kernel<128, false, false><<<gemmBlocks, 256>>>(x, W1, N);
    aggregate_kernel<128, true><<<aggBlocks, T>>>(b1, nullptr, N);

    gemm_kernel<128, true, true><<<gemmBlocks, 256>>>(nullptr, W2, N);
    aggregate_kernel<128, true><<<aggBlocks, T>>>(b2, nullptr, N);

    gemm_kernel<64, true, true><<<gemmBlocks, 256>>>(nullptr, W3, N);
    aggregate_kernel<64, false><<<aggBlocks, T>>>(b3, out, N);
}

// round 9
// speedup vs baseline: 2.1560x; 1.1255x over previous
#include <cuda_runtime.h>

// ---------------------------------------------------------------------------
// 3-layer GCN, symmetric norm D^{-1/2}(A+I)D^{-1/2}, self-loops.
// N=50000, E=640000, features 128 -> 128 -> 128 -> 64.
// R9: prep chain overlapped with GEMM1 via stream fork/join (graph branch),
// F=64 aggregate packs 2 nodes per warp.
// ---------------------------------------------------------------------------

#define MAX_N 50048
#define MAX_E 640000
#define SCAN_CHUNK 1024

__device__ __align__(16) float g_H[MAX_N * 128];
__device__ __align__(16) float g_B[MAX_N * 128];
__device__ __align__(16) float g_enorm[MAX_E];
__device__ __align__(16) int   g_src[MAX_E];
__device__ int   g_rowptr[MAX_N + 1];
__device__ int   g_cnt[MAX_N];                      // ZERO between replays
__device__ int   g_bsum[(MAX_N + SCAN_CHUNK - 1) / SCAN_CHUNK];
__device__ float g_dinv[MAX_N];
__device__ int   g_is64;

// ---------------------------------------------------------------------------
// f32x2 helpers
// ---------------------------------------------------------------------------
__device__ __forceinline__ unsigned long long dup_f32(float w) {
    unsigned long long r;
    asm("mov.b64 %0, {%1, %1};" : "=l"(r) : "f"(w));
    return r;
}
__device__ __forceinline__ void ffma2(unsigned long long& d,
                                      unsigned long long a,
                                      unsigned long long b) {
    asm("fma.rn.f32x2 %0, %1, %2, %0;" : "+l"(d) : "l"(a), "l"(b));
}
__device__ __forceinline__ void unpack2(unsigned long long v, float& lo, float& hi) {
    asm("mov.b64 {%0, %1}, %2;" : "=f"(lo), "=f"(hi) : "l"(v));
}

// ---------------------------------------------------------------------------
// Prep
// ---------------------------------------------------------------------------
__global__ void detect_dtype_kernel(const void* __restrict__ ei, int E, int N) {
    int tid = threadIdx.x;
    const long long* p = (const long long*)ei;
    int take = E < 128 ? E : 128;
    int bad = 0;
    for (int j = tid * 4; j < tid * 4 + 4; j++) {
        if (j < take) {
            long long v = p[j];
            if (v < 0 || v >= (long long)N) bad = 1;
        }
    }
    unsigned m = __ballot_sync(0xffffffffu, bad);
    if (tid == 0) g_is64 = (m == 0u);
}

__device__ __forceinline__ void decode_edge(const void* ei, int E, int e,
                                            int& s, int& d) {
    if (g_is64) {
        const long long* p = (const long long*)ei;
        s = (int)p[e];
        d = (int)p[E + e];
    } else {
        const int* p = (const int*)ei;
        s = p[e];
        d = p[E + e];
    }
}

__global__ void count_kernel(const void* __restrict__ ei, int E) {
    int e = blockIdx.x * blockDim.x + threadIdx.x;
    if (e >= E) return;
    int d;
    if (g_is64) d = (int)((const long long*)ei)[E + e];
    else        d = ((const int*)ei)[E + e];
    atomicAdd(&g_cnt[d], 1);
}

__global__ void scan1_kernel(int n) {
    __shared__ int warpsum[8];
    const int tid = threadIdx.x, lane = tid & 31, wid = tid >> 5;
    const int base = blockIdx.x * SCAN_CHUNK + tid * 4;

    int v[4] = {0, 0, 0, 0};
    if (base + 3 < n) {
        *reinterpret_cast<int4*>(v) = *reinterpret_cast<const int4*>(&g_cnt[base]);
    } else {
        for (int j = 0; j < 4; j++) if (base + j < n) v[j] = g_cnt[base + j];
    }
    #pragma unroll
    for (int j = 0; j < 4; j++)
        if (base + j < n) g_dinv[base + j] = rsqrtf((float)v[j] + 1.0f);

    int t0 = v[0], t1 = t0 + v[1], t2 = t1 + v[2], t3 = t2 + v[3];
    int x = t3;
    #pragma unroll
    for (int off = 1; off < 32; off <<= 1) {
        int t = __shfl_up_sync(0xffffffffu, x, off);
        if (lane >= off) x += t;
    }
    if (lane == 31) warpsum[wid] = x;
    __syncthreads();
    if (wid == 0 && lane < 8) {
        int w = warpsum[lane];
        #pragma unroll
        for (int off = 1; off < 8; off <<= 1) {
            int t = __shfl_up_sync(0xffu, w, off);
            if (lane >= off) w += t;
        }
        warpsum[lane] = w;
    }
    __syncthreads();

    int off = (x - t3) + (wid > 0 ? warpsum[wid - 1] : 0);
    int pre[4] = {0, t0, t1, t2};
    #pragma unroll
    for (int j = 0; j < 4; j++)
        if (base + j < n) g_rowptr[base + j] = off + pre[j];

    if (tid == 255) g_bsum[blockIdx.x] = warpsum[7];
}

__global__ void scan2_kernel(int nb, int n) {
    __shared__ int ws[2];
    int tid = threadIdx.x, lane = tid & 31, wid = tid >> 5;
    int v = (tid < nb) ? g_bsum[tid] : 0;
    int x = v;
    #pragma unroll
    for (int off = 1; off < 32; off <<= 1) {
        int t = __shfl_up_sync(0xffffffffu, x, off);
        if (lane >= off) x += t;
    }
    if (lane == 31) ws[wid] = x;
    __syncthreads();
    if (wid == 1) x += ws[0];
    if (tid < nb) g_bsum[tid] = x - v;
    if (tid == nb - 1) g_rowptr[n] = x;
}

__global__ void scan3_kernel(int n) {
    int i = blockIdx.x * blockDim.x + threadIdx.x;
    if (i < n) g_rowptr[i] += g_bsum[i >> 10];
}

__global__ void fill_kernel(const void* __restrict__ ei, int E) {
    int e = blockIdx.x * blockDim.x + threadIdx.x;
    if (e >= E) return;
    int s, d;
    decode_edge(ei, E, e, s, d);
    int pos = g_rowptr[d] + atomicSub(&g_cnt[d], 1) - 1;
    g_src[pos] = s;
    g_enorm[pos] = g_dinv[s] * g_dinv[d];
}

// ---------------------------------------------------------------------------
// FFMA2 register-tiled SGEMM, software-pipelined: g_H = X @ W
// ---------------------------------------------------------------------------
template <int BN, bool RELU, bool FROM_GB>
__global__ __launch_bounds__(256, 2)
void gemm_kernel(const float* __restrict__ Xin,
                 const float* __restrict__ W, int N) {
    constexpr int BM = 128, BK = 16;
    constexpr int TN = BN / 16;
    constexpr int WI = (BK * BN) / 1024;

    __shared__ float Xs[BK][BM + 4];
    __shared__ float Ws[BK][BN];

    const float* __restrict__ X = FROM_GB ? (const float*)g_B : Xin;

    const int tid = threadIdx.x;
    const int tx = tid & 15;
    const int ty = tid >> 4;
    const int rowBase = blockIdx.x * BM;

    const int xrow0 = tid >> 2, xkq0 = tid & 3;
    const int xrow1 = (tid + 256) >> 2, xkq1 = (tid + 256) & 3;
    const int r0 = rowBase + xrow0, r1 = rowBase + xrow1;

    float4 xr[2], wr[2];

    auto load_tile = [&](int kc) {
        xr[0] = make_float4(0.f, 0.f, 0.f, 0.f);
        xr[1] = make_float4(0.f, 0.f, 0.f, 0.f);
        if (r0 < N)
            xr[0] = *reinterpret_cast<const float4*>(&X[(size_t)r0 * 128 + kc + xkq0 * 4]);
        if (r1 < N)
            xr[1] = *reinterpret_cast<const float4*>(&X[(size_t)r1 * 128 + kc + xkq1 * 4]);
        if (RELU) {
            xr[0].x = fmaxf(xr[0].x, 0.f); xr[0].y = fmaxf(xr[0].y, 0.f);
            xr[0].z = fmaxf(xr[0].z, 0.f); xr[0].w = fmaxf(xr[0].w, 0.f);
            xr[1].x = fmaxf(xr[1].x, 0.f); xr[1].y = fmaxf(xr[1].y, 0.f);
            xr[1].z = fmaxf(xr[1].z, 0.f); xr[1].w = fmaxf(xr[1].w, 0.f);
        }
        #pragma unroll
        for (int i = 0; i < WI; i++) {
            int j = tid + 256 * i;
            int kk = j / (BN / 4);
            int cc = j % (BN / 4);
            wr[i] = *reinterpret_cast<const float4*>(&W[(size_t)(kc + kk) * BN + cc * 4]);
        }
    };
    auto store_tile = [&]() {
        Xs[xkq0 * 4 + 0][xrow0] = xr[0].x;
        Xs[xkq0 * 4 + 1][xrow0] = xr[0].y;
        Xs[xkq0 * 4 + 2][xrow0] = xr[0].z;
        Xs[xkq0 * 4 + 3][xrow0] = xr[0].w;
        Xs[xkq1 * 4 + 0][xrow1] = xr[1].x;
        Xs[xkq1 * 4 + 1][xrow1] = xr[1].y;
        Xs[xkq1 * 4 + 2][xrow1] = xr[1].z;
        Xs[xkq1 * 4 + 3][xrow1] = xr[1].w;
        #pragma unroll
        for (int i = 0; i < WI; i++) {
            int j = tid + 256 * i;
            int kk = j / (BN / 4);
            int cc = j % (BN / 4);
            *reinterpret_cast<float4*>(&Ws[kk][cc * 4]) = wr[i];
        }
    };

    unsigned long long acc2[4][TN];
    #pragma unroll
    for (int i = 0; i < 4; i++)
        #pragma unroll
        for (int j = 0; j < TN; j++) acc2[i][j] = 0ull;

    load_tile(0);
    store_tile();
    __syncthreads();

    for (int t = 0; t < 128 / BK; t++) {
        if (t + 1 < 128 / BK) load_tile((t + 1) * BK);

        #pragma unroll
        for (int k = 0; k < BK; k++) {
            const ulonglong2* ap =
                reinterpret_cast<const ulonglong2*>(&Xs[k][ty * 8]);
            ulonglong2 a01 = ap[0];
            ulonglong2 a23 = ap[1];
            unsigned long long a2[4] = {a01.x, a01.y, a23.x, a23.y};

            float bw[TN];
            #pragma unroll
            for (int j = 0; j < TN; j += 4)
                *reinterpret_cast<float4*>(&bw[j]) =
                    *reinterpret_cast<const float4*>(&Ws[k][tx * TN + j]);
            unsigned long long b2[TN];
            #pragma unroll
            for (int j = 0; j < TN; j++) b2[j] = dup_f32(bw[j]);

            #pragma unroll
            for (int rp = 0; rp < 4; rp++)
                #pragma unroll
                for (int j = 0; j < TN; j++)
                    ffma2(acc2[rp][j], a2[rp], b2[j]);
        }
        __syncthreads();
        if (t + 1 < 128 / BK) {
            store_tile();
            __syncthreads();
        }
    }

    #pragma unroll
    for (int rp = 0; rp < 4; rp++) {
        float h0[TN], h1[TN];
        #pragma unroll
        for (int j = 0; j < TN; j++) unpack2(acc2[rp][j], h0[j], h1[j]);
        int row0 = rowBase + ty * 8 + 2 * rp;
        #pragma unroll
        for (int half = 0; half < 2; half++) {
            int row = row0 + half;
            if (row >= N) continue;
            float* h = half ? h1 : h0;
            size_t base = (size_t)row * BN + tx * TN;
            #pragma unroll
            for (int j = 0; j < TN; j += 4)
                *reinterpret_cast<float4*>(&g_H[base + j]) =
                    *reinterpret_cast<const float4*>(&h[j]);
        }
    }
}

// ---------------------------------------------------------------------------
// F=128 aggregation: warp per node, 8-edge unroll, fused self-loop+bias.
// ---------------------------------------------------------------------------
__global__ void aggregate128_kernel(const float* __restrict__ bias, int N) {
    int warp = (blockIdx.x * blockDim.x + threadIdx.x) >> 5;
    int lane = threadIdx.x & 31;
    if (warp >= N) return;

    int e = g_rowptr[warp];
    const int end = g_rowptr[warp + 1];

    const float4* __restrict__ H4 = reinterpret_cast<const float4*>(g_H);
    float di = g_dinv[warp];
    float s = di * di;
    float4 hd = H4[(size_t)warp * 32 + lane];
    float4 bb = reinterpret_cast<const float4*>(bias)[lane];
    float4 acc = make_float4(fmaf(hd.x, s, bb.x), fmaf(hd.y, s, bb.y),
                             fmaf(hd.z, s, bb.z), fmaf(hd.w, s, bb.w));

    for (; e + 7 < end; e += 8) {
        int   si[8];
        float ni[8];
        #pragma unroll
        for (int j = 0; j < 8; j++) { si[j] = g_src[e + j]; ni[j] = g_enorm[e + j]; }
        float4 v[8];
        #pragma unroll
        for (int j = 0; j < 8; j++) v[j] = H4[(size_t)si[j] * 32 + lane];
        #pragma unroll
        for (int j = 0; j < 8; j++) {
            acc.x = fmaf(v[j].x, ni[j], acc.x);
            acc.y = fmaf(v[j].y, ni[j], acc.y);
            acc.z = fmaf(v[j].z, ni[j], acc.z);
            acc.w = fmaf(v[j].w, ni[j], acc.w);
        }
    }
    for (; e < end; e++) {
        int s0 = g_src[e];
        float n0 = g_enorm[e];
        float4 v0 = H4[(size_t)s0 * 32 + lane];
        acc.x = fmaf(v0.x, n0, acc.x);
        acc.y = fmaf(v0.y, n0, acc.y);
        acc.z = fmaf(v0.z, n0, acc.z);
        acc.w = fmaf(v0.w, n0, acc.w);
    }

    reinterpret_cast<float4*>(g_B)[(size_t)warp * 32 + lane] = acc;
}

// ---------------------------------------------------------------------------
// F=64 aggregation: TWO nodes per warp (16 lanes each), writes d_out.
// ---------------------------------------------------------------------------
__global__ void aggregate64_kernel(const float* __restrict__ bias,
                                   float* __restrict__ outp, int N) {
    int warp = (blockIdx.x * blockDim.x + threadIdx.x) >> 5;
    int lane = threadIdx.x & 31;
    int node = warp * 2 + (lane >> 4);
    int l16 = lane & 15;
    if (node >= N) return;

    int e = g_rowptr[node];
    const int end = g_rowptr[node + 1];

    const float4* __restrict__ H4 = reinterpret_cast<const float4*>(g_H);
    float di = g_dinv[node];
    float s = di * di;
    float4 hd = H4[(size_t)node * 16 + l16];
    float4 bb = reinterpret_cast<const float4*>(bias)[l16];
    float4 acc = make_float4(fmaf(hd.x, s, bb.x), fmaf(hd.y, s, bb.y),
                             fmaf(hd.z, s, bb.z), fmaf(hd.w, s, bb.w));

    for (; e + 3 < end; e += 4) {
        int s0 = g_src[e], s1 = g_src[e + 1], s2 = g_src[e + 2], s3 = g_src[e + 3];
        float n0 = g_enorm[e], n1 = g_enorm[e + 1];
        float n2 = g_enorm[e + 2], n3 = g_enorm[e + 3];
        float4 v0 = H4[(size_t)s0 * 16 + l16];
        float4 v1 = H4[(size_t)s1 * 16 + l16];
        float4 v2 = H4[(size_t)s2 * 16 + l16];
        float4 v3 = H4[(size_t)s3 * 16 + l16];
        acc.x += v0.x * n0 + v1.x * n1 + v2.x * n2 + v3.x * n3;
        acc.y += v0.y * n0 + v1.y * n1 + v2.y * n2 + v3.y * n3;
        acc.z += v0.z * n0 + v1.z * n1 + v2.z * n2 + v3.z * n3;
        acc.w += v0.w * n0 + v1.w * n1 + v2.w * n2 + v3.w * n3;
    }
    for (; e < end; e++) {
        int s0 = g_src[e];
        float n0 = g_enorm[e];
        float4 v0 = H4[(size_t)s0 * 16 + l16];
        acc.x = fmaf(v0.x, n0, acc.x);
        acc.y = fmaf(v0.y, n0, acc.y);
        acc.z = fmaf(v0.z, n0, acc.z);
        acc.w = fmaf(v0.w, n0, acc.w);
    }

    reinterpret_cast<float4*>(outp)[(size_t)node * 16 + l16] = acc;
}

// ---------------------------------------------------------------------------
// Launch: prep chain on side stream, overlapped with GEMM1 (graph fork/join).
// ---------------------------------------------------------------------------
extern "C" void kernel_launch(void* const* d_in, const int* in_sizes, int n_in,
                              void* d_out, int out_size) {
    const float* x  = (const float*)d_in[0];
    const void*  ei = d_in[1];
    const float* W1 = (const float*)d_in[2];
    const float* b1 = (const float*)d_in[3];
    const float* W2 = (const float*)d_in[4];
    const float* b2 = (const float*)d_in[5];
    const float* W3 = (const float*)d_in[6];
    const float* b3 = (const float*)d_in[7];
    float* out = (float*)d_out;

    const int N = in_sizes[0] / 128;
    const int E = in_sizes[1] / 2;
    const int T = 256;
    const int nb = (N + SCAN_CHUNK - 1) / SCAN_CHUNK;

    static cudaStream_t s2 = nullptr;
    static cudaEvent_t evFork = nullptr, evJoin = nullptr;
    if (!s2) {
        cudaStreamCreateWithFlags(&s2, cudaStreamNonBlocking);
        cudaEventCreateWithFlags(&evFork, cudaEventDisableTiming);
        cudaEventCreateWithFlags(&evJoin, cudaEventDisableTiming);
    }

    // fork: prep chain runs on s2 concurrently with GEMM1 on main stream
    cudaEventRecord(evFork, 0);
    cudaStreamWaitEvent(s2, evFork, 0);

    detect_dtype_kernel<<<1, 32, 0, s2>>>(ei, E, N);
    count_kernel<<<(E + T - 1) / T, T, 0, s2>>>(ei, E);
    scan1_kernel<<<nb, 256, 0, s2>>>(N);
    scan2_kernel<<<1, 64, 0, s2>>>(nb, N);
    scan3_kernel<<<(N + T - 1) / T, T, 0, s2>>>(N);
    fill_kernel<<<(E + T - 1) / T, T, 0, s2>>>(ei, E);
    cudaEventRecord(evJoin, s2);

    const int gemmBlocks = (N + 127) / 128;
    const int agg128Blocks = (N * 32 + T - 1) / T;
    const int agg64Blocks = (((N + 1) / 2) * 32 + T - 1) / T;

    // layer 1 GEMM overlaps prep
    gemm_kernel<128, false, false><<<gemmBlocks, 256>>>(x, W1, N);

    // join: aggregation needs CSR + H
    cudaStreamWaitEvent(0, evJoin, 0);
    aggregate128_kernel<<<agg128Blocks, T>>>(b1, N);

    gemm_kernel<128, true, true><<<gemmBlocks, 256>>>(nullptr, W2, N);
    aggregate128_kernel<<<agg128Blocks, T>>>(b2, N);

    gemm_kernel<64, true, true><<<gemmBlocks, 256>>>(nullptr, W3, N);
    aggregate64_kernel<<<agg64Blocks, T>>>(b3, out, N);
}

// round 10
// speedup vs baseline: 2.2260x; 1.0325x over previous
#include <cuda_runtime.h>

// ---------------------------------------------------------------------------
// 3-layer GCN, symmetric norm D^{-1/2}(A+I)D^{-1/2}, self-loops.
// N=50000, E=640000, features 128 -> 128 -> 128 -> 64.
// R10: two-stream row-half pipeline (agg(k) half overlaps gemm(k+1) half),
// prep overlapped with gemm1.
// ---------------------------------------------------------------------------

#define MAX_N 50048
#define MAX_E 640000
#define SCAN_CHUNK 1024

__device__ __align__(16) float g_H[MAX_N * 128];
__device__ __align__(16) float g_B[MAX_N * 128];
__device__ __align__(16) float g_enorm[MAX_E];
__device__ __align__(16) int   g_src[MAX_E];
__device__ int   g_rowptr[MAX_N + 1];
__device__ int   g_cnt[MAX_N];                      // ZERO between replays
__device__ int   g_bsum[(MAX_N + SCAN_CHUNK - 1) / SCAN_CHUNK];
__device__ float g_dinv[MAX_N];
__device__ int   g_is64;

// ---------------------------------------------------------------------------
// f32x2 helpers
// ---------------------------------------------------------------------------
__device__ __forceinline__ unsigned long long dup_f32(float w) {
    unsigned long long r;
    asm("mov.b64 %0, {%1, %1};" : "=l"(r) : "f"(w));
    return r;
}
__device__ __forceinline__ void ffma2(unsigned long long& d,
                                      unsigned long long a,
                                      unsigned long long b) {
    asm("fma.rn.f32x2 %0, %1, %2, %0;" : "+l"(d) : "l"(a), "l"(b));
}
__device__ __forceinline__ void unpack2(unsigned long long v, float& lo, float& hi) {
    asm("mov.b64 {%0, %1}, %2;" : "=f"(lo), "=f"(hi) : "l"(v));
}

// ---------------------------------------------------------------------------
// Prep
// ---------------------------------------------------------------------------
__global__ void detect_dtype_kernel(const void* __restrict__ ei, int E, int N) {
    int tid = threadIdx.x;
    const long long* p = (const long long*)ei;
    int take = E < 128 ? E : 128;
    int bad = 0;
    for (int j = tid * 4; j < tid * 4 + 4; j++) {
        if (j < take) {
            long long v = p[j];
            if (v < 0 || v >= (long long)N) bad = 1;
        }
    }
    unsigned m = __ballot_sync(0xffffffffu, bad);
    if (tid == 0) g_is64 = (m == 0u);
}

__device__ __forceinline__ void decode_edge(const void* ei, int E, int e,
                                            int& s, int& d) {
    if (g_is64) {
        const long long* p = (const long long*)ei;
        s = (int)p[e];
        d = (int)p[E + e];
    } else {
        const int* p = (const int*)ei;
        s = p[e];
        d = p[E + e];
    }
}

__global__ void count_kernel(const void* __restrict__ ei, int E) {
    int e = blockIdx.x * blockDim.x + threadIdx.x;
    if (e >= E) return;
    int d;
    if (g_is64) d = (int)((const long long*)ei)[E + e];
    else        d = ((const int*)ei)[E + e];
    atomicAdd(&g_cnt[d], 1);
}

__global__ void scan1_kernel(int n) {
    __shared__ int warpsum[8];
    const int tid = threadIdx.x, lane = tid & 31, wid = tid >> 5;
    const int base = blockIdx.x * SCAN_CHUNK + tid * 4;

    int v[4] = {0, 0, 0, 0};
    if (base + 3 < n) {
        *reinterpret_cast<int4*>(v) = *reinterpret_cast<const int4*>(&g_cnt[base]);
    } else {
        for (int j = 0; j < 4; j++) if (base + j < n) v[j] = g_cnt[base + j];
    }
    #pragma unroll
    for (int j = 0; j < 4; j++)
        if (base + j < n) g_dinv[base + j] = rsqrtf((float)v[j] + 1.0f);

    int t0 = v[0], t1 = t0 + v[1], t2 = t1 + v[2], t3 = t2 + v[3];
    int x = t3;
    #pragma unroll
    for (int off = 1; off < 32; off <<= 1) {
        int t = __shfl_up_sync(0xffffffffu, x, off);
        if (lane >= off) x += t;
    }
    if (lane == 31) warpsum[wid] = x;
    __syncthreads();
    if (wid == 0 && lane < 8) {
        int w = warpsum[lane];
        #pragma unroll
        for (int off = 1; off < 8; off <<= 1) {
            int t = __shfl_up_sync(0xffu, w, off);
            if (lane >= off) w += t;
        }
        warpsum[lane] = w;
    }
    __syncthreads();

    int off = (x - t3) + (wid > 0 ? warpsum[wid - 1] : 0);
    int pre[4] = {0, t0, t1, t2};
    #pragma unroll
    for (int j = 0; j < 4; j++)
        if (base + j < n) g_rowptr[base + j] = off + pre[j];

    if (tid == 255) g_bsum[blockIdx.x] = warpsum[7];
}

__global__ void scan2_kernel(int nb, int n) {
    __shared__ int ws[2];
    int tid = threadIdx.x, lane = tid & 31, wid = tid >> 5;
    int v = (tid < nb) ? g_bsum[tid] : 0;
    int x = v;
    #pragma unroll
    for (int off = 1; off < 32; off <<= 1) {
        int t = __shfl_up_sync(0xffffffffu, x, off);
        if (lane >= off) x += t;
    }
    if (lane == 31) ws[wid] = x;
    __syncthreads();
    if (wid == 1) x += ws[0];
    if (tid < nb) g_bsum[tid] = x - v;
    if (tid == nb - 1) g_rowptr[n] = x;
}

__global__ void scan3_kernel(int n) {
    int i = blockIdx.x * blockDim.x + threadIdx.x;
    if (i < n) g_rowptr[i] += g_bsum[i >> 10];
}

__global__ void fill_kernel(const void* __restrict__ ei, int E) {
    int e = blockIdx.x * blockDim.x + threadIdx.x;
    if (e >= E) return;
    int s, d;
    decode_edge(ei, E, e, s, d);
    int pos = g_rowptr[d] + atomicSub(&g_cnt[d], 1) - 1;
    g_src[pos] = s;
    g_enorm[pos] = g_dinv[s] * g_dinv[d];
}

// ---------------------------------------------------------------------------
// FFMA2 register-tiled SGEMM over row range [rowBegin, rowEnd): g_H = X @ W
// ---------------------------------------------------------------------------
template <int BN, bool RELU, bool FROM_GB>
__global__ __launch_bounds__(256, 2)
void gemm_kernel(const float* __restrict__ Xin,
                 const float* __restrict__ W, int rowBegin, int rowEnd) {
    constexpr int BM = 128, BK = 16;
    constexpr int TN = BN / 16;
    constexpr int WI = (BK * BN) / 1024;

    __shared__ float Xs[BK][BM + 4];
    __shared__ float Ws[BK][BN];

    const float* __restrict__ X = FROM_GB ? (const float*)g_B : Xin;

    const int tid = threadIdx.x;
    const int tx = tid & 15;
    const int ty = tid >> 4;
    const int rowBase = rowBegin + blockIdx.x * BM;

    const int xrow0 = tid >> 2, xkq0 = tid & 3;
    const int xrow1 = (tid + 256) >> 2, xkq1 = (tid + 256) & 3;
    const int r0 = rowBase + xrow0, r1 = rowBase + xrow1;

    float4 xr[2], wr[2];

    auto load_tile = [&](int kc) {
        xr[0] = make_float4(0.f, 0.f, 0.f, 0.f);
        xr[1] = make_float4(0.f, 0.f, 0.f, 0.f);
        if (r0 < rowEnd)
            xr[0] = *reinterpret_cast<const float4*>(&X[(size_t)r0 * 128 + kc + xkq0 * 4]);
        if (r1 < rowEnd)
            xr[1] = *reinterpret_cast<const float4*>(&X[(size_t)r1 * 128 + kc + xkq1 * 4]);
        if (RELU) {
            xr[0].x = fmaxf(xr[0].x, 0.f); xr[0].y = fmaxf(xr[0].y, 0.f);
            xr[0].z = fmaxf(xr[0].z, 0.f); xr[0].w = fmaxf(xr[0].w, 0.f);
            xr[1].x = fmaxf(xr[1].x, 0.f); xr[1].y = fmaxf(xr[1].y, 0.f);
            xr[1].z = fmaxf(xr[1].z, 0.f); xr[1].w = fmaxf(xr[1].w, 0.f);
        }
        #pragma unroll
        for (int i = 0; i < WI; i++) {
            int j = tid + 256 * i;
            int kk = j / (BN / 4);
            int cc = j % (BN / 4);
            wr[i] = *reinterpret_cast<const float4*>(&W[(size_t)(kc + kk) * BN + cc * 4]);
        }
    };
    auto store_tile = [&]() {
        Xs[xkq0 * 4 + 0][xrow0] = xr[0].x;
        Xs[xkq0 * 4 + 1][xrow0] = xr[0].y;
        Xs[xkq0 * 4 + 2][xrow0] = xr[0].z;
        Xs[xkq0 * 4 + 3][xrow0] = xr[0].w;
        Xs[xkq1 * 4 + 0][xrow1] = xr[1].x;
        Xs[xkq1 * 4 + 1][xrow1] = xr[1].y;
        Xs[xkq1 * 4 + 2][xrow1] = xr[1].z;
        Xs[xkq1 * 4 + 3][xrow1] = xr[1].w;
        #pragma unroll
        for (int i = 0; i < WI; i++) {
            int j = tid + 256 * i;
            int kk = j / (BN / 4);
            int cc = j % (BN / 4);
            *reinterpret_cast<float4*>(&Ws[kk][cc * 4]) = wr[i];
        }
    };

    unsigned long long acc2[4][TN];
    #pragma unroll
    for (int i = 0; i < 4; i++)
        #pragma unroll
        for (int j = 0; j < TN; j++) acc2[i][j] = 0ull;

    load_tile(0);
    store_tile();
    __syncthreads();

    for (int t = 0; t < 128 / BK; t++) {
        if (t + 1 < 128 / BK) load_tile((t + 1) * BK);

        #pragma unroll
        for (int k = 0; k < BK; k++) {
            const ulonglong2* ap =
                reinterpret_cast<const ulonglong2*>(&Xs[k][ty * 8]);
            ulonglong2 a01 = ap[0];
            ulonglong2 a23 = ap[1];
            unsigned long long a2[4] = {a01.x, a01.y, a23.x, a23.y};

            float bw[TN];
            #pragma unroll
            for (int j = 0; j < TN; j += 4)
                *reinterpret_cast<float4*>(&bw[j]) =
                    *reinterpret_cast<const float4*>(&Ws[k][tx * TN + j]);
            unsigned long long b2[TN];
            #pragma unroll
            for (int j = 0; j < TN; j++) b2[j] = dup_f32(bw[j]);

            #pragma unroll
            for (int rp = 0; rp < 4; rp++)
                #pragma unroll
                for (int j = 0; j < TN; j++)
                    ffma2(acc2[rp][j], a2[rp], b2[j]);
        }
        __syncthreads();
        if (t + 1 < 128 / BK) {
            store_tile();
            __syncthreads();
        }
    }

    #pragma unroll
    for (int rp = 0; rp < 4; rp++) {
        float h0[TN], h1[TN];
        #pragma unroll
        for (int j = 0; j < TN; j++) unpack2(acc2[rp][j], h0[j], h1[j]);
        int row0 = rowBase + ty * 8 + 2 * rp;
        #pragma unroll
        for (int half = 0; half < 2; half++) {
            int row = row0 + half;
            if (row >= rowEnd) continue;
            float* h = half ? h1 : h0;
            size_t base = (size_t)row * BN + tx * TN;
            #pragma unroll
            for (int j = 0; j < TN; j += 4)
                *reinterpret_cast<float4*>(&g_H[base + j]) =
                    *reinterpret_cast<const float4*>(&h[j]);
        }
    }
}

// ---------------------------------------------------------------------------
// F=128 aggregation over node range [begin, end): warp per node.
// ---------------------------------------------------------------------------
__global__ void aggregate128_kernel(const float* __restrict__ bias,
                                    int begin, int end) {
    int node = begin + ((blockIdx.x * blockDim.x + threadIdx.x) >> 5);
    int lane = threadIdx.x & 31;
    if (node >= end) return;

    int e = g_rowptr[node];
    const int eend = g_rowptr[node + 1];

    const float4* __restrict__ H4 = reinterpret_cast<const float4*>(g_H);
    float di = g_dinv[node];
    float s = di * di;
    float4 hd = H4[(size_t)node * 32 + lane];
    float4 bb = reinterpret_cast<const float4*>(bias)[lane];
    float4 acc = make_float4(fmaf(hd.x, s, bb.x), fmaf(hd.y, s, bb.y),
                             fmaf(hd.z, s, bb.z), fmaf(hd.w, s, bb.w));

    for (; e + 7 < eend; e += 8) {
        int   si[8];
        float ni[8];
        #pragma unroll
        for (int j = 0; j < 8; j++) { si[j] = __ldg(&g_src[e + j]); ni[j] = __ldg(&g_enorm[e + j]); }
        float4 v[8];
        #pragma unroll
        for (int j = 0; j < 8; j++) v[j] = H4[(size_t)si[j] * 32 + lane];
        #pragma unroll
        for (int j = 0; j < 8; j++) {
            acc.x = fmaf(v[j].x, ni[j], acc.x);
            acc.y = fmaf(v[j].y, ni[j], acc.y);
            acc.z = fmaf(v[j].z, ni[j], acc.z);
            acc.w = fmaf(v[j].w, ni[j], acc.w);
        }
    }
    for (; e < eend; e++) {
        int s0 = __ldg(&g_src[e]);
        float n0 = __ldg(&g_enorm[e]);
        float4 v0 = H4[(size_t)s0 * 32 + lane];
        acc.x = fmaf(v0.x, n0, acc.x);
        acc.y = fmaf(v0.y, n0, acc.y);
        acc.z = fmaf(v0.z, n0, acc.z);
        acc.w = fmaf(v0.w, n0, acc.w);
    }

    reinterpret_cast<float4*>(g_B)[(size_t)node * 32 + lane] = acc;
}

// ---------------------------------------------------------------------------
// F=64 aggregation over [begin, end): two nodes per warp, writes d_out.
// ---------------------------------------------------------------------------
__global__ void aggregate64_kernel(const float* __restrict__ bias,
                                   float* __restrict__ outp,
                                   int begin, int end) {
    int warp = (blockIdx.x * blockDim.x + threadIdx.x) >> 5;
    int lane = threadIdx.x & 31;
    int node = begin + warp * 2 + (lane >> 4);
    int l16 = lane & 15;
    if (node >= end) return;

    int e = g_rowptr[node];
    const int eend = g_rowptr[node + 1];

    const float4* __restrict__ H4 = reinterpret_cast<const float4*>(g_H);
    float di = g_dinv[node];
    float s = di * di;
    float4 hd = H4[(size_t)node * 16 + l16];
    float4 bb = reinterpret_cast<const float4*>(bias)[l16];
    float4 acc = make_float4(fmaf(hd.x, s, bb.x), fmaf(hd.y, s, bb.y),
                             fmaf(hd.z, s, bb.z), fmaf(hd.w, s, bb.w));

    for (; e + 3 < eend; e += 4) {
        int s0 = __ldg(&g_src[e]), s1 = __ldg(&g_src[e + 1]);
        int s2 = __ldg(&g_src[e + 2]), s3 = __ldg(&g_src[e + 3]);
        float n0 = __ldg(&g_enorm[e]), n1 = __ldg(&g_enorm[e + 1]);
        float n2 = __ldg(&g_enorm[e + 2]), n3 = __ldg(&g_enorm[e + 3]);
        float4 v0 = H4[(size_t)s0 * 16 + l16];
        float4 v1 = H4[(size_t)s1 * 16 + l16];
        float4 v2 = H4[(size_t)s2 * 16 + l16];
        float4 v3 = H4[(size_t)s3 * 16 + l16];
        acc.x += v0.x * n0 + v1.x * n1 + v2.x * n2 + v3.x * n3;
        acc.y += v0.y * n0 + v1.y * n1 + v2.y * n2 + v3.y * n3;
        acc.z += v0.z * n0 + v1.z * n1 + v2.z * n2 + v3.z * n3;
        acc.w += v0.w * n0 + v1.w * n1 + v2.w * n2 + v3.w * n3;
    }
    for (; e < eend; e++) {
        int s0 = __ldg(&g_src[e]);
        float n0 = __ldg(&g_enorm[e]);
        float4 v0 = H4[(size_t)s0 * 16 + l16];
        acc.x = fmaf(v0.x, n0, acc.x);
        acc.y = fmaf(v0.y, n0, acc.y);
        acc.z = fmaf(v0.z, n0, acc.z);
        acc.w = fmaf(v0.w, n0, acc.w);
    }

    reinterpret_cast<float4*>(outp)[(size_t)node * 16 + l16] = acc;
}

// ---------------------------------------------------------------------------
// Launch: two-stream row-half pipeline.
// ---------------------------------------------------------------------------
extern "C" void kernel_launch(void* const* d_in, const int* in_sizes, int n_in,
                              void* d_out, int out_size) {
    const float* x  = (const float*)d_in[0];
    const void*  ei = d_in[1];
    const float* W1 = (const float*)d_in[2];
    const float* b1 = (const float*)d_in[3];
    const float* W2 = (const float*)d_in[4];
    const float* b2 = (const float*)d_in[5];
    const float* W3 = (const float*)d_in[6];
    const float* b3 = (const float*)d_in[7];
    float* out = (float*)d_out;

    const int N = in_sizes[0] / 128;
    const int E = in_sizes[1] / 2;
    const int T = 256;
    const int nb = (N + SCAN_CHUNK - 1) / SCAN_CHUNK;
    const int Nh = (N + 1) / 2;           // half boundary

    static cudaStream_t s2 = nullptr;
    static cudaEvent_t ev[8];
    if (!s2) {
        cudaStreamCreateWithFlags(&s2, cudaStreamNonBlocking);
        for (int i = 0; i < 8; i++)
            cudaEventCreateWithFlags(&ev[i], cudaEventDisableTiming);
    }

    // grid helpers
    const int gemmB_h0 = (Nh + 127) / 128;
    const int gemmB_h1 = (N - Nh + 127) / 128;
    const int aggB_h0 = (Nh * 32 + T - 1) / T;
    const int aggB_h1 = ((N - Nh) * 32 + T - 1) / T;
    const int agg64B_h0 = (((Nh + 1) / 2) * 32 + T - 1) / T;
    const int agg64B_h1 = (((N - Nh + 1) / 2) * 32 + T - 1) / T;

    // ---- fork: prep on s2 ---------------------------------------------------
    cudaEventRecord(ev[0], 0);
    cudaStreamWaitEvent(s2, ev[0], 0);

    detect_dtype_kernel<<<1, 32, 0, s2>>>(ei, E, N);
    count_kernel<<<(E + T - 1) / T, T, 0, s2>>>(ei, E);
    scan1_kernel<<<nb, 256, 0, s2>>>(N);
    scan2_kernel<<<1, 64, 0, s2>>>(nb, N);
    scan3_kernel<<<(N + T - 1) / T, T, 0, s2>>>(N);
    fill_kernel<<<(E + T - 1) / T, T, 0, s2>>>(ei, E);
    cudaEventRecord(ev[1], s2);           // prep done

    // ---- gemm1 (full) on s0, overlapping prep ----
    gemm_kernel<128, false, false><<<(N + 127) / 128, 256>>>(x, W1, 0, N);
    cudaEventRecord(ev[2], 0);            // H1 done

    // ---- layer-1 agg / layer-2 gemm halves ----
    cudaStreamWaitEvent(0, ev[1], 0);     // s0 needs CSR
    aggregate128_kernel<<<aggB_h0, T>>>(b1, 0, Nh);
    gemm_kernel<128, true, true><<<gemmB_h0, 256>>>(nullptr, W2, 0, Nh);
    cudaEventRecord(ev[3], 0);            // gemm2 h0 done

    cudaStreamWaitEvent(s2, ev[2], 0);    // s2 needs H1 (prep in program order)
    aggregate128_kernel<<<aggB_h1, T, 0, s2>>>(b1, Nh, N);
    gemm_kernel<128, true, true><<<gemmB_h1, 256, 0, s2>>>(nullptr, W2, Nh, N);
    cudaEventRecord(ev[4], s2);           // gemm2 h1 done

    // ---- layer-2 agg / layer-3 gemm halves ----
    cudaStreamWaitEvent(0, ev[4], 0);     // agg2 needs full H2
    aggregate128_kernel<<<aggB_h0, T>>>(b2, 0, Nh);
    gemm_kernel<64, true, true><<<gemmB_h0, 256>>>(nullptr, W3, 0, Nh);
    cudaEventRecord(ev[5], 0);            // gemm3 h0 done

    cudaStreamWaitEvent(s2, ev[3], 0);
    aggregate128_kernel<<<aggB_h1, T, 0, s2>>>(b2, Nh, N);
    gemm_kernel<64, true, true><<<gemmB_h1, 256, 0, s2>>>(nullptr, W3, Nh, N);
    cudaEventRecord(ev[6], s2);           // gemm3 h1 done

    // ---- layer-3 agg halves -> d_out ----
    cudaStreamWaitEvent(0, ev[6], 0);
    aggregate64_kernel<<<agg64B_h0, T>>>(b3, out, 0, Nh);

    cudaStreamWaitEvent(s2, ev[5], 0);
    aggregate64_kernel<<<agg64B_h1, T, 0, s2>>>(b3, out, Nh, N);
    cudaEventRecord(ev[7], s2);

    // join everything back to the capture-origin stream
    cudaStreamWaitEvent(0, ev[7], 0);
}